// round 7
// baseline (speedup 1.0000x reference)
#include <cuda_runtime.h>
#include <math.h>
#include <stdint.h>

#define NPTS 1024
#define KNB 20
#define BATCH 8
#define CEPS 1e-5f
#define CSLOPE 0.2f

// ---------------- scratch (no allocations allowed) ----------------
__device__ float g_cat[(size_t)BATCH * 512 * NPTS];   // x1(0:64) x2(64:128) x3(128:256) x4(256:512)
__device__ float g_gram[(size_t)BATCH * NPTS * NPTS];
__device__ float g_xx[BATCH * NPTS];
__device__ int   g_idx[(size_t)BATCH * NPTS * KNB];
__device__ float g_Z[(size_t)BATCH * NPTS * 512];     // Z = x @ [W1t | Wdt]  per batch
__device__ float g_Wt[256 * 512];                     // packed weights, 4 segments
__device__ float g_pmax[BATCH * NPTS * 8];            // embed pooling partials
__device__ float g_psum[BATCH * NPTS * 8];
__device__ float g_h0[BATCH * 2048];
__device__ float g_h1[BATCH * 512];
__device__ float g_h2[BATCH * 256];

// Wt segment offsets (floats): layer K*2O sizes 384, 8192, 16384, 65536
#define WOFF0 0
#define WOFF1 384
#define WOFF2 8576
#define WOFF3 24960
#define WTOT  90496

// ================= tf32 MMA helpers =================
__device__ __forceinline__ uint32_t f2tf(float f) {
    uint32_t u; asm("cvt.rna.tf32.f32 %0, %1;" : "=r"(u) : "f"(f)); return u;
}
__device__ __forceinline__ void mma8(float* c, const uint32_t* a, const uint32_t* b) {
    asm volatile(
        "mma.sync.aligned.m16n8k8.row.col.f32.tf32.tf32.f32 "
        "{%0,%1,%2,%3}, {%4,%5,%6,%7}, {%8,%9}, {%0,%1,%2,%3};\n"
        : "+f"(c[0]), "+f"(c[1]), "+f"(c[2]), "+f"(c[3])
        : "r"(a[0]), "r"(a[1]), "r"(a[2]), "r"(a[3]), "r"(b[0]), "r"(b[1]));
}

// ================= 3xTF32 split GEMM, A given K-major =================
// C[M][N] = sum_k A[k][m] * B[k][n].  A is [K][M] (lda), B is [K][N] (ldb).
// 128x128 tile, 8 warps (2x4), KC=16, K bounds-guarded (zero-fill).
__global__ void __launch_bounds__(256, 1) gemm_split(
    const float* __restrict__ A, const float* __restrict__ B, float* __restrict__ Cc,
    int K, int lda, int ldb, int ldc,
    size_t sAz, size_t sBz, size_t sCz)
{
    constexpr int KC = 16;
    const int z = blockIdx.z;
    const int m0 = blockIdx.y * 128, n0 = blockIdx.x * 128;
    const float* Ab = A + z * sAz + m0;
    const float* Bb = B + z * sBz + n0;
    float* Cb = Cc + z * sCz;

    __shared__ uint32_t Ash[KC][136], Asl[KC][136];
    __shared__ uint32_t Bsh[KC][136], Bsl[KC][136];

    const int tid = threadIdx.x, lane = tid & 31, wrp = tid >> 5;
    const int wm = wrp >> 2, wn = wrp & 3;
    const int qr = lane >> 2, qc = lane & 3;

    float acc[4][4][4];
    #pragma unroll
    for (int i = 0; i < 4; i++)
        #pragma unroll
        for (int j = 0; j < 4; j++)
            #pragma unroll
            for (int q = 0; q < 4; q++) acc[i][j][q] = 0.f;

    int lr[2], lc[2];
    #pragma unroll
    for (int i = 0; i < 2; i++) { int idx = tid + i * 256; lr[i] = idx >> 5; lc[i] = (idx & 31) * 4; }

    const float4 z4 = make_float4(0.f, 0.f, 0.f, 0.f);
    float4 ra[2], rb[2];
    #pragma unroll
    for (int i = 0; i < 2; i++) {
        bool ok = lr[i] < K;
        ra[i] = ok ? *(const float4*)(Ab + (size_t)lr[i] * lda + lc[i]) : z4;
        rb[i] = ok ? *(const float4*)(Bb + (size_t)lr[i] * ldb + lc[i]) : z4;
    }

    const int KT = (K + KC - 1) / KC;
    for (int kt = 0; kt < KT; kt++) {
        #pragma unroll
        for (int i = 0; i < 2; i++) {
            float va[4] = {ra[i].x, ra[i].y, ra[i].z, ra[i].w};
            float vb[4] = {rb[i].x, rb[i].y, rb[i].z, rb[i].w};
            #pragma unroll
            for (int q = 0; q < 4; q++) {
                uint32_t h = f2tf(va[q]);
                Ash[lr[i]][lc[i] + q] = h;
                Asl[lr[i]][lc[i] + q] = f2tf(va[q] - __uint_as_float(h));
                uint32_t g = f2tf(vb[q]);
                Bsh[lr[i]][lc[i] + q] = g;
                Bsl[lr[i]][lc[i] + q] = f2tf(vb[q] - __uint_as_float(g));
            }
        }
        __syncthreads();
        if (kt + 1 < KT) {
            const float* An = Ab + (size_t)(kt + 1) * KC * lda;
            const float* Bn = Bb + (size_t)(kt + 1) * KC * ldb;
            #pragma unroll
            for (int i = 0; i < 2; i++) {
                bool ok = (kt + 1) * KC + lr[i] < K;
                ra[i] = ok ? *(const float4*)(An + (size_t)lr[i] * lda + lc[i]) : z4;
                rb[i] = ok ? *(const float4*)(Bn + (size_t)lr[i] * ldb + lc[i]) : z4;
            }
        }
        #pragma unroll
        for (int kk = 0; kk < 2; kk++) {
            uint32_t afh[4][4], afl[4][4];
            #pragma unroll
            for (int mt = 0; mt < 4; mt++) {
                int r = wm * 64 + mt * 16 + qr, c = kk * 8 + qc;
                afh[mt][0] = Ash[c][r];     afh[mt][1] = Ash[c][r + 8];
                afh[mt][2] = Ash[c + 4][r]; afh[mt][3] = Ash[c + 4][r + 8];
                afl[mt][0] = Asl[c][r];     afl[mt][1] = Asl[c][r + 8];
                afl[mt][2] = Asl[c + 4][r]; afl[mt][3] = Asl[c + 4][r + 8];
            }
            uint32_t bfh[4][2], bfl[4][2];
            #pragma unroll
            for (int nt = 0; nt < 4; nt++) {
                int cc = wn * 32 + nt * 8 + qr, rr = kk * 8 + qc;
                bfh[nt][0] = Bsh[rr][cc]; bfh[nt][1] = Bsh[rr + 4][cc];
                bfl[nt][0] = Bsl[rr][cc]; bfl[nt][1] = Bsl[rr + 4][cc];
            }
            #pragma unroll
            for (int mt = 0; mt < 4; mt++)
                #pragma unroll
                for (int nt = 0; nt < 4; nt++) {
                    mma8(acc[mt][nt], afh[mt], bfh[nt]);
                    mma8(acc[mt][nt], afl[mt], bfh[nt]);
                    mma8(acc[mt][nt], afh[mt], bfl[nt]);
                }
        }
        __syncthreads();
    }

    #pragma unroll
    for (int mt = 0; mt < 4; mt++)
        #pragma unroll
        for (int nt = 0; nt < 4; nt++) {
            int r = m0 + wm * 64 + mt * 16 + qr;
            int cc = n0 + wn * 32 + nt * 8 + 2 * qc;
            *(float2*)(Cb + (size_t)r * ldc + cc)       = make_float2(acc[mt][nt][0], acc[mt][nt][1]);
            *(float2*)(Cb + (size_t)(r + 8) * ldc + cc) = make_float2(acc[mt][nt][2], acc[mt][nt][3]);
        }
}

// ================= embedding GEMM fused with BN+lrelu+pool partials =================
// e[o][n] = sum_c we[o][c]*cat[c][n]; partial max/sum over the 128-col tile.
__global__ void __launch_bounds__(256, 1) gemm_embed(
    const float* __restrict__ A,   // we [1024][512] row-major
    const float* __restrict__ B,   // cat [512][NPTS] per batch
    const float* __restrict__ bne)
{
    constexpr int KC = 16;
    constexpr int K = 512;
    const int z = blockIdx.z;
    const int m0 = blockIdx.y * 128, n0 = blockIdx.x * 128;
    const float* Ab = A + (size_t)m0 * K;
    const float* Bb = B + (size_t)z * 512 * NPTS + n0;

    __shared__ uint32_t Ash[128][KC + 4], Asl[128][KC + 4];
    __shared__ uint32_t Bsh[KC][136], Bsl[KC][136];

    const int tid = threadIdx.x, lane = tid & 31, wrp = tid >> 5;
    const int wm = wrp >> 2, wn = wrp & 3;
    const int qr = lane >> 2, qc = lane & 3;

    float acc[4][4][4];
    #pragma unroll
    for (int i = 0; i < 4; i++)
        #pragma unroll
        for (int j = 0; j < 4; j++)
            #pragma unroll
            for (int q = 0; q < 4; q++) acc[i][j][q] = 0.f;

    int ar[2], ac[2], br[2], bc[2];
    #pragma unroll
    for (int i = 0; i < 2; i++) {
        int idx = tid + i * 256;
        ar[i] = idx >> 2;  ac[i] = (idx & 3) * 4;
        br[i] = idx >> 5;  bc[i] = (idx & 31) * 4;
    }

    float4 ra[2], rb[2];
    #pragma unroll
    for (int i = 0; i < 2; i++) {
        ra[i] = *(const float4*)(Ab + (size_t)ar[i] * K + ac[i]);
        rb[i] = *(const float4*)(Bb + (size_t)br[i] * NPTS + bc[i]);
    }

    const int KT = K / KC;
    for (int kt = 0; kt < KT; kt++) {
        #pragma unroll
        for (int i = 0; i < 2; i++) {
            float va[4] = {ra[i].x, ra[i].y, ra[i].z, ra[i].w};
            float vb[4] = {rb[i].x, rb[i].y, rb[i].z, rb[i].w};
            #pragma unroll
            for (int q = 0; q < 4; q++) {
                uint32_t h = f2tf(va[q]);
                Ash[ar[i]][ac[i] + q] = h;
                Asl[ar[i]][ac[i] + q] = f2tf(va[q] - __uint_as_float(h));
                uint32_t g = f2tf(vb[q]);
                Bsh[br[i]][bc[i] + q] = g;
                Bsl[br[i]][bc[i] + q] = f2tf(vb[q] - __uint_as_float(g));
            }
        }
        __syncthreads();
        if (kt + 1 < KT) {
            const float* An = Ab + (kt + 1) * KC;
            const float* Bn = Bb + (size_t)(kt + 1) * KC * NPTS;
            #pragma unroll
            for (int i = 0; i < 2; i++) {
                ra[i] = *(const float4*)(An + (size_t)ar[i] * K + ac[i]);
                rb[i] = *(const float4*)(Bn + (size_t)br[i] * NPTS + bc[i]);
            }
        }
        #pragma unroll
        for (int kk = 0; kk < 2; kk++) {
            uint32_t afh[4][4], afl[4][4];
            #pragma unroll
            for (int mt = 0; mt < 4; mt++) {
                int r = wm * 64 + mt * 16 + qr, c = kk * 8 + qc;
                afh[mt][0] = Ash[r][c];     afh[mt][1] = Ash[r + 8][c];
                afh[mt][2] = Ash[r][c + 4]; afh[mt][3] = Ash[r + 8][c + 4];
                afl[mt][0] = Asl[r][c];     afl[mt][1] = Asl[r + 8][c];
                afl[mt][2] = Asl[r][c + 4]; afl[mt][3] = Asl[r + 8][c + 4];
            }
            uint32_t bfh[4][2], bfl[4][2];
            #pragma unroll
            for (int nt = 0; nt < 4; nt++) {
                int cc = wn * 32 + nt * 8 + qr, rr = kk * 8 + qc;
                bfh[nt][0] = Bsh[rr][cc]; bfh[nt][1] = Bsh[rr + 4][cc];
                bfl[nt][0] = Bsl[rr][cc]; bfl[nt][1] = Bsl[rr + 4][cc];
            }
            #pragma unroll
            for (int mt = 0; mt < 4; mt++)
                #pragma unroll
                for (int nt = 0; nt < 4; nt++) {
                    mma8(acc[mt][nt], afh[mt], bfh[nt]);
                    mma8(acc[mt][nt], afl[mt], bfh[nt]);
                    mma8(acc[mt][nt], afh[mt], bfl[nt]);
                }
        }
        __syncthreads();
    }

    // fused epilogue: BN + lrelu + per-row (o) max/sum over this 128-col tile
    __shared__ float smax[128][5], ssum[128][5];
    #pragma unroll
    for (int mt = 0; mt < 4; mt++) {
        int rl = wm * 64 + mt * 16 + qr;        // local rows rl, rl+8
        int o0 = m0 + rl, o1 = o0 + 8;
        float s0 = bne[o0] / sqrtf(bne[3072 + o0] + CEPS);
        float b0 = bne[1024 + o0], u0 = bne[2048 + o0];
        float s1 = bne[o1] / sqrtf(bne[3072 + o1] + CEPS);
        float b1 = bne[1024 + o1], u1 = bne[2048 + o1];
        float mx0 = -INFINITY, sm0 = 0.f, mx1 = -INFINITY, sm1 = 0.f;
        #pragma unroll
        for (int nt = 0; nt < 4; nt++) {
            #pragma unroll
            for (int p = 0; p < 2; p++) {
                float y0 = (acc[mt][nt][p] - u0) * s0 + b0;
                y0 = (y0 > 0.f) ? y0 : CSLOPE * y0;
                mx0 = fmaxf(mx0, y0); sm0 += y0;
                float y1 = (acc[mt][nt][2 + p] - u1) * s1 + b1;
                y1 = (y1 > 0.f) ? y1 : CSLOPE * y1;
                mx1 = fmaxf(mx1, y1); sm1 += y1;
            }
        }
        #pragma unroll
        for (int off = 1; off <= 2; off <<= 1) {
            mx0 = fmaxf(mx0, __shfl_xor_sync(0xffffffffu, mx0, off));
            sm0 += __shfl_xor_sync(0xffffffffu, sm0, off);
            mx1 = fmaxf(mx1, __shfl_xor_sync(0xffffffffu, mx1, off));
            sm1 += __shfl_xor_sync(0xffffffffu, sm1, off);
        }
        if (qc == 0) {
            smax[rl][wn] = mx0; ssum[rl][wn] = sm0;
            smax[rl + 8][wn] = mx1; ssum[rl + 8][wn] = sm1;
        }
    }
    __syncthreads();
    if (tid < 128) {
        float mx = -INFINITY, sm = 0.f;
        #pragma unroll
        for (int w = 0; w < 4; w++) { mx = fmaxf(mx, smax[tid][w]); sm += ssum[tid][w]; }
        size_t o = (size_t)z * NPTS + m0 + tid;
        g_pmax[o * 8 + blockIdx.x] = mx;
        g_psum[o * 8 + blockIdx.x] = sm;
    }
}

__global__ void efinish_kernel() {
    int i = blockIdx.x * 256 + threadIdx.x;   // 8192 (b,o)
    int b = i >> 10, o = i & 1023;
    float mx = -INFINITY, sm = 0.f;
    #pragma unroll
    for (int t = 0; t < 8; t++) { mx = fmaxf(mx, g_pmax[(size_t)i * 8 + t]); sm += g_psum[(size_t)i * 8 + t]; }
    g_h0[b * 2048 + o] = mx;
    g_h0[b * 2048 + 1024 + o] = sm * (1.0f / 1024.0f);
}

// ================= weight packing (all 4 layers, one launch) =================
__global__ void wprep_all(const float* __restrict__ w0, const float* __restrict__ w1,
                          const float* __restrict__ w2, const float* __restrict__ w3) {
    int i = blockIdx.x * 256 + threadIdx.x;
    if (i >= WTOT) return;
    const float* w; int C, O, loc;
    if (i < WOFF1)      { w = w0; C = 3;   O = 64;  loc = i - WOFF0; }
    else if (i < WOFF2) { w = w1; C = 64;  O = 64;  loc = i - WOFF1; }
    else if (i < WOFF3) { w = w2; C = 64;  O = 128; loc = i - WOFF2; }
    else                { w = w3; C = 128; O = 256; loc = i - WOFF3; }
    int N2 = 2 * O, kp = loc / N2, j = loc - kp * N2;
    float v;
    if (j < O) v = w[(size_t)j * 2 * C + kp];
    else { int o = j - O; v = w[(size_t)o * 2 * C + C + kp] - w[(size_t)o * 2 * C + kp]; }
    g_Wt[i] = v;
}

// ================= top-20 selection (lane-cached local max) =================
__device__ __forceinline__ void select20(float d[32], int lane, int* myidx) {
    float lm = -INFINITY; int lj = 0;
    #pragma unroll
    for (int j = 0; j < 32; j++) if (d[j] > lm) { lm = d[j]; lj = j; }
    for (int k = 0; k < KNB; k++) {
        float bv = lm; int bidx = lj * 32 + lane;
        #pragma unroll
        for (int off = 16; off > 0; off >>= 1) {
            float ov = __shfl_xor_sync(0xffffffffu, bv, off);
            int   oi = __shfl_xor_sync(0xffffffffu, bidx, off);
            if (ov > bv || (ov == bv && oi < bidx)) { bv = ov; bidx = oi; }
        }
        if (lane == (bidx & 31)) {
            int jj = bidx >> 5;
            lm = -INFINITY; lj = 0;
            #pragma unroll
            for (int j = 0; j < 32; j++) {
                if (j == jj) d[j] = -INFINITY;
                if (d[j] > lm) { lm = d[j]; lj = j; }
            }
        }
        if (lane == 0) myidx[k] = bidx;
    }
}

// generic: score from materialized gram + xx
__global__ void __launch_bounds__(256) topk_kernel() {
    const int tid = threadIdx.x, lane = tid & 31;
    const int gw = blockIdx.x * 8 + (tid >> 5);
    const int b = gw >> 10, n = gw & 1023;
    const float* Grow = g_gram + ((size_t)b * NPTS + n) * NPTS;
    const float* xxb = g_xx + b * NPTS;
    float d[32];
    #pragma unroll
    for (int j = 0; j < 32; j++) {
        int m = j * 32 + lane;
        d[j] = 2.f * Grow[m] - xxb[m];
    }
    select20(d, lane, g_idx + ((size_t)b * NPTS + n) * KNB);
}

// block-1 fused: distances from raw x (C=3) computed inline, exact fp32
__global__ void __launch_bounds__(256) topk3_kernel(const float* __restrict__ x) {
    const int tid = threadIdx.x, lane = tid & 31;
    const int gw = blockIdx.x * 8 + (tid >> 5);
    const int b = gw >> 10, n = gw & 1023;
    const float* xb = x + (size_t)b * 3 * NPTS;
    float c0 = xb[n], c1 = xb[NPTS + n], c2 = xb[2 * NPTS + n];
    float d[32];
    #pragma unroll
    for (int j = 0; j < 32; j++) {
        int m = j * 32 + lane;
        float v0 = xb[m], v1 = xb[NPTS + m], v2 = xb[2 * NPTS + m];
        float dot = fmaf(v2, c2, fmaf(v1, c1, fmaf(v0, c0, 0.f)));
        float xxm = fmaf(v2, v2, fmaf(v1, v1, fmaf(v0, v0, 0.f)));
        d[j] = 2.f * dot - xxm;
    }
    select20(d, lane, g_idx + ((size_t)b * NPTS + n) * KNB);
}

// ================= misc support =================
template<int C>
__global__ void xx_kernel(const float* __restrict__ base) {
    const int b = blockIdx.y;
    const int m = blockIdx.x * 256 + threadIdx.x;
    const float* xb = base + (size_t)b * 512 * NPTS;
    float s = 0.f;
    #pragma unroll 8
    for (int c = 0; c < C; c++) {
        float v = xb[(size_t)c * NPTS + m];
        s = fmaf(v, v, s);
    }
    g_xx[b * NPTS + m] = s;
}

// conv epilogue from Z: max_k Z1[jid_k][o] + Z2[n][o], then BN (gamma>0) + lrelu
__global__ void cepi_kernel(const float* __restrict__ bnp, int O, int cout_off) {
    const int b = blockIdx.y, n = blockIdx.x, o = threadIdx.x;
    __shared__ int jid[KNB];
    if (o < KNB) jid[o] = g_idx[((size_t)b * NPTS + n) * KNB + o];
    __syncthreads();
    const int ld = 2 * O;
    const size_t rowbase = (size_t)b * NPTS;
    float mx = -INFINITY;
    #pragma unroll 4
    for (int k = 0; k < KNB; k++)
        mx = fmaxf(mx, g_Z[(rowbase + jid[k]) * ld + o]);
    mx += g_Z[(rowbase + n) * ld + O + o];
    float gg = bnp[o], bb = bnp[O + o], mm = bnp[2 * O + o], vv = bnp[3 * O + o];
    float scale = gg / sqrtf(vv + CEPS);
    float y = (mx - mm) * scale + bb;
    y = (y > 0.f) ? y : CSLOPE * y;
    g_cat[(size_t)b * 512 * NPTS + (size_t)(cout_off + o) * NPTS + n] = y;
}

// ================= MLP head =================
__global__ void mlp_bn_kernel(const float* __restrict__ w, const float* __restrict__ bnp,
                              const float* __restrict__ hin, float* __restrict__ hout,
                              int IN, int ON) {
    const int b = blockIdx.x, o = threadIdx.x;
    const float* hr = hin + (size_t)b * IN;
    const float* wr = w + (size_t)o * IN;
    float a0 = 0.f, a1 = 0.f, a2 = 0.f, a3 = 0.f;
    for (int c = 0; c < IN; c += 4) {
        a0 = fmaf(hr[c],     wr[c],     a0);
        a1 = fmaf(hr[c + 1], wr[c + 1], a1);
        a2 = fmaf(hr[c + 2], wr[c + 2], a2);
        a3 = fmaf(hr[c + 3], wr[c + 3], a3);
    }
    float acc = (a0 + a1) + (a2 + a3);
    float gg = bnp[o], bb = bnp[ON + o], mm = bnp[2 * ON + o], vv = bnp[3 * ON + o];
    float scale = gg / sqrtf(vv + CEPS);
    float y = (acc - mm) * scale + bb;
    hout[(size_t)b * ON + o] = (y > 0.f) ? y : CSLOPE * y;
}

__global__ void final_kernel(const float* __restrict__ w, const float* __restrict__ bias,
                             float* __restrict__ out) {
    const int b = blockIdx.x, o = threadIdx.x;
    const float* hr = g_h2 + b * 256;
    const float* wr = w + (size_t)o * 256;
    float a0 = 0.f, a1 = 0.f, a2 = 0.f, a3 = 0.f;
    for (int c = 0; c < 256; c += 4) {
        a0 = fmaf(hr[c],     wr[c],     a0);
        a1 = fmaf(hr[c + 1], wr[c + 1], a1);
        a2 = fmaf(hr[c + 2], wr[c + 2], a2);
        a3 = fmaf(hr[c + 3], wr[c + 3], a3);
    }
    out[b * 64 + o] = bias[o] + (a0 + a1) + (a2 + a3);
}

// ================= launch =================
extern "C" void kernel_launch(void* const* d_in, const int* in_sizes, int n_in,
                              void* d_out, int out_size) {
    const float* x    = (const float*)d_in[0];
    const float* w0   = (const float*)d_in[1];
    const float* w1   = (const float*)d_in[2];
    const float* w2   = (const float*)d_in[3];
    const float* w3   = (const float*)d_in[4];
    const float* bn0  = (const float*)d_in[5];
    const float* bn1  = (const float*)d_in[6];
    const float* bn2  = (const float*)d_in[7];
    const float* bn3  = (const float*)d_in[8];
    const float* we   = (const float*)d_in[9];
    const float* bne  = (const float*)d_in[10];
    const float* wf0  = (const float*)d_in[11];
    const float* bnf0 = (const float*)d_in[12];
    const float* wf1  = (const float*)d_in[13];
    const float* bnf1 = (const float*)d_in[14];
    const float* wfin = (const float*)d_in[15];
    const float* bfin = (const float*)d_in[16];

    float *h0, *h1, *h2, *Zp, *Wtp, *catp, *gramp;
    cudaGetSymbolAddress((void**)&h0, g_h0);
    cudaGetSymbolAddress((void**)&h1, g_h1);
    cudaGetSymbolAddress((void**)&h2, g_h2);
    cudaGetSymbolAddress((void**)&Zp, g_Z);
    cudaGetSymbolAddress((void**)&Wtp, g_Wt);
    cudaGetSymbolAddress((void**)&catp, g_cat);
    cudaGetSymbolAddress((void**)&gramp, g_gram);

    dim3 gxx(NPTS / 256, BATCH);
    dim3 gpn(NPTS, BATCH);
    const size_t sCat = (size_t)512 * NPTS;
    const size_t sG = (size_t)NPTS * NPTS;

    wprep_all<<<(WTOT + 255) / 256, 256>>>(w0, w1, w2, w3);

    // ---- block 1: x (C=3) -> x1 (64) at cat[0:64] ----
    topk3_kernel<<<1024, 256>>>(x);
    gemm_split<<<dim3(1, 8, BATCH), 256>>>(x, Wtp + WOFF0, Zp, 3, NPTS, 128, 128,
                                           (size_t)3 * NPTS, 0, (size_t)NPTS * 128);
    cepi_kernel<<<gpn, 64>>>(bn0, 64, 0);

    // ---- block 2: x1 (C=64) -> x2 (64) at cat[64:128] ----
    xx_kernel<64><<<gxx, 256>>>(catp);
    gemm_split<<<dim3(8, 8, BATCH), 256>>>(catp, catp, gramp, 64, NPTS, NPTS, NPTS,
                                           sCat, sCat, sG);
    topk_kernel<<<1024, 256>>>();
    gemm_split<<<dim3(1, 8, BATCH), 256>>>(catp, Wtp + WOFF1, Zp, 64, NPTS, 128, 128,
                                           sCat, 0, (size_t)NPTS * 128);
    cepi_kernel<<<gpn, 64>>>(bn1, 64, 64);

    // ---- block 3: x2 (C=64) -> x3 (128) at cat[128:256] ----
    xx_kernel<64><<<gxx, 256>>>(catp + (size_t)64 * NPTS);
    gemm_split<<<dim3(8, 8, BATCH), 256>>>(catp + (size_t)64 * NPTS, catp + (size_t)64 * NPTS,
                                           gramp, 64, NPTS, NPTS, NPTS, sCat, sCat, sG);
    topk_kernel<<<1024, 256>>>();
    gemm_split<<<dim3(2, 8, BATCH), 256>>>(catp + (size_t)64 * NPTS, Wtp + WOFF2, Zp, 64,
                                           NPTS, 256, 256, sCat, 0, (size_t)NPTS * 256);
    cepi_kernel<<<gpn, 128>>>(bn2, 128, 128);

    // ---- block 4: x3 (C=128) -> x4 (256) at cat[256:512] ----
    xx_kernel<128><<<gxx, 256>>>(catp + (size_t)128 * NPTS);
    gemm_split<<<dim3(8, 8, BATCH), 256>>>(catp + (size_t)128 * NPTS, catp + (size_t)128 * NPTS,
                                           gramp, 128, NPTS, NPTS, NPTS, sCat, sCat, sG);
    topk_kernel<<<1024, 256>>>();
    gemm_split<<<dim3(4, 8, BATCH), 256>>>(catp + (size_t)128 * NPTS, Wtp + WOFF3, Zp, 128,
                                           NPTS, 512, 512, sCat, 0, (size_t)NPTS * 512);
    cepi_kernel<<<gpn, 256>>>(bn3, 256, 256);

    // ---- embedding GEMM with fused BN+lrelu+pool partials ----
    gemm_embed<<<dim3(8, 8, BATCH), 256>>>(we, catp, bne);
    efinish_kernel<<<32, 256>>>();

    // ---- MLP head ----
    mlp_bn_kernel<<<BATCH, 512>>>(wf0, bnf0, h0, h1, 2048, 512);
    mlp_bn_kernel<<<BATCH, 256>>>(wf1, bnf1, h1, h2, 512, 256);
    final_kernel<<<BATCH, 64>>>(wfin, bfin, (float*)d_out);
}

// round 8
// speedup vs baseline: 1.1704x; 1.1704x over previous
#include <cuda_runtime.h>
#include <cuda_fp16.h>
#include <math.h>
#include <stdint.h>

#define NPTS 1024
#define KNB 20
#define BATCH 8
#define CEPS 1e-5f
#define CSLOPE 0.2f

// ---------------- scratch (no allocations allowed) ----------------
__device__ float g_cat[(size_t)BATCH * 512 * NPTS];   // x1(0:64) x2(64:128) x3(128:256) x4(256:512)
__device__ float g_gram[(size_t)BATCH * NPTS * NPTS];
__device__ float g_xx[BATCH * NPTS];
__device__ int   g_idx[(size_t)BATCH * NPTS * KNB];
__device__ float g_Z[(size_t)BATCH * NPTS * 512];     // Z = x @ [W1t | Wdt] per batch
__device__ float g_Wt[256 * 512];                     // packed conv weights, 4 segments (K-major [kp][2O])
__device__ float g_weT[512 * 1024];                   // we transposed K-major [c][o]
__device__ float g_pmax[BATCH * NPTS * 8];            // embed pooling partials
__device__ float g_psum[BATCH * NPTS * 8];
__device__ float g_h0[BATCH * 2048];

#define WOFF0 0
#define WOFF1 384
#define WOFF2 8576
#define WOFF3 24960
#define WTOT  90496

// ================= fp16 MMA helpers =================
__device__ __forceinline__ void mma16(float* c, const uint32_t* a, const uint32_t* b) {
    asm volatile(
        "mma.sync.aligned.m16n8k16.row.col.f32.f16.f16.f32 "
        "{%0,%1,%2,%3}, {%4,%5,%6,%7}, {%8,%9}, {%0,%1,%2,%3};\n"
        : "+f"(c[0]), "+f"(c[1]), "+f"(c[2]), "+f"(c[3])
        : "r"(a[0]), "r"(a[1]), "r"(a[2]), "r"(a[3]), "r"(b[0]), "r"(b[1]));
}

// stage one 128-col x 32-k tile from a K-major fp32 source into split half2 smem.
// Layout: S[kpair][col], kpair packs (2kp, 2kp+1) as half2. Kr = remaining valid k rows.
__device__ __forceinline__ void stage_km(const float* __restrict__ src, int ld, int Kr, int tid,
                                         uint32_t (*Sh)[136], uint32_t (*Sl)[136]) {
    #pragma unroll
    for (int i = 0; i < 2; i++) {
        int lin = tid + i * 256;
        int kp = lin >> 5, cq = (lin & 31) * 4;
        int k0 = 2 * kp;
        float4 zz = make_float4(0.f, 0.f, 0.f, 0.f);
        float4 r0 = (k0     < Kr) ? *(const float4*)(src + (size_t)k0 * ld + cq) : zz;
        float4 r1 = (k0 + 1 < Kr) ? *(const float4*)(src + (size_t)(k0 + 1) * ld + cq) : zz;
        float v0[4] = {r0.x, r0.y, r0.z, r0.w};
        float v1[4] = {r1.x, r1.y, r1.z, r1.w};
        #pragma unroll
        for (int j = 0; j < 4; j++) {
            __half h0 = __float2half_rn(v0[j]);
            __half h1 = __float2half_rn(v1[j]);
            __half l0 = __float2half_rn(v0[j] - __half2float(h0));
            __half l1 = __float2half_rn(v1[j] - __half2float(h1));
            __half2 hh = __halves2half2(h0, h1);
            __half2 ll = __halves2half2(l0, l1);
            Sh[kp][cq + j] = *(uint32_t*)&hh;
            Sl[kp][cq + j] = *(uint32_t*)&ll;
        }
    }
}

// ================= fp16-split GEMM =================
// C[M][N] = sum_k A[k][m] * B[k][n]; A [K][lda], B [K][ldb], both K-major fp32.
// 128x128 tile, 8 warps (2x4), KC=32. POOL: embed epilogue (BN+lrelu+max/mean partials).
template<bool POOL>
__global__ void __launch_bounds__(256) gemm16(
    const float* __restrict__ A, const float* __restrict__ B, float* __restrict__ Cc,
    const float* __restrict__ bne,
    int K, int lda, int ldb, int ldc, size_t sAz, size_t sBz, size_t sCz)
{
    const int z = blockIdx.z;
    const int m0 = blockIdx.y * 128, n0 = blockIdx.x * 128;
    const float* Ab = A + z * sAz + m0;
    const float* Bb = B + z * sBz + n0;

    __shared__ uint32_t Ah[16][136], Al[16][136], Bh[16][136], Bl[16][136];

    const int tid = threadIdx.x, lane = tid & 31, wrp = tid >> 5;
    const int wm = wrp >> 2, wn = wrp & 3;
    const int qr = lane >> 2, qc = lane & 3;

    float acc[4][4][4];
    #pragma unroll
    for (int i = 0; i < 4; i++)
        #pragma unroll
        for (int j = 0; j < 4; j++)
            #pragma unroll
            for (int q = 0; q < 4; q++) acc[i][j][q] = 0.f;

    const int KT = (K + 31) / 32;
    for (int kt = 0; kt < KT; kt++) {
        int Kr = K - kt * 32;
        stage_km(Ab + (size_t)kt * 32 * lda, lda, Kr, tid, Ah, Al);
        stage_km(Bb + (size_t)kt * 32 * ldb, ldb, Kr, tid, Bh, Bl);
        __syncthreads();
        #pragma unroll
        for (int kk = 0; kk < 2; kk++) {
            const int kb = kk * 8;
            uint32_t ah[4][4], al[4][4], bh[4][2], bl[4][2];
            #pragma unroll
            for (int mt = 0; mt < 4; mt++) {
                int R = wm * 64 + mt * 16;
                ah[mt][0] = Ah[kb + qc][R + qr];     ah[mt][1] = Ah[kb + qc][R + qr + 8];
                ah[mt][2] = Ah[kb + qc + 4][R + qr]; ah[mt][3] = Ah[kb + qc + 4][R + qr + 8];
                al[mt][0] = Al[kb + qc][R + qr];     al[mt][1] = Al[kb + qc][R + qr + 8];
                al[mt][2] = Al[kb + qc + 4][R + qr]; al[mt][3] = Al[kb + qc + 4][R + qr + 8];
            }
            #pragma unroll
            for (int nt = 0; nt < 4; nt++) {
                int C0 = wn * 32 + nt * 8;
                bh[nt][0] = Bh[kb + qc][C0 + qr]; bh[nt][1] = Bh[kb + qc + 4][C0 + qr];
                bl[nt][0] = Bl[kb + qc][C0 + qr]; bl[nt][1] = Bl[kb + qc + 4][C0 + qr];
            }
            #pragma unroll
            for (int mt = 0; mt < 4; mt++)
                #pragma unroll
                for (int nt = 0; nt < 4; nt++) {
                    mma16(acc[mt][nt], ah[mt], bh[nt]);
                    mma16(acc[mt][nt], al[mt], bh[nt]);
                    mma16(acc[mt][nt], ah[mt], bl[nt]);
                }
        }
        __syncthreads();
    }

    if (!POOL) {
        float* Cb = Cc + z * sCz;
        #pragma unroll
        for (int mt = 0; mt < 4; mt++)
            #pragma unroll
            for (int nt = 0; nt < 4; nt++) {
                int r = m0 + wm * 64 + mt * 16 + qr;
                int cc = n0 + wn * 32 + nt * 8 + 2 * qc;
                *(float2*)(Cb + (size_t)r * ldc + cc)       = make_float2(acc[mt][nt][0], acc[mt][nt][1]);
                *(float2*)(Cb + (size_t)(r + 8) * ldc + cc) = make_float2(acc[mt][nt][2], acc[mt][nt][3]);
            }
    } else {
        // embed epilogue: BN + lrelu + per-row (o) max/sum over this 128-col tile
        __shared__ float smax[128][5], ssum[128][5];
        #pragma unroll
        for (int mt = 0; mt < 4; mt++) {
            int rl = wm * 64 + mt * 16 + qr;
            int o0 = m0 + rl, o1 = o0 + 8;
            float s0 = bne[o0] / sqrtf(bne[3072 + o0] + CEPS);
            float b0 = bne[1024 + o0], u0 = bne[2048 + o0];
            float s1 = bne[o1] / sqrtf(bne[3072 + o1] + CEPS);
            float b1 = bne[1024 + o1], u1 = bne[2048 + o1];
            float mx0 = -INFINITY, sm0 = 0.f, mx1 = -INFINITY, sm1 = 0.f;
            #pragma unroll
            for (int nt = 0; nt < 4; nt++) {
                #pragma unroll
                for (int p = 0; p < 2; p++) {
                    float y0 = (acc[mt][nt][p] - u0) * s0 + b0;
                    y0 = (y0 > 0.f) ? y0 : CSLOPE * y0;
                    mx0 = fmaxf(mx0, y0); sm0 += y0;
                    float y1 = (acc[mt][nt][2 + p] - u1) * s1 + b1;
                    y1 = (y1 > 0.f) ? y1 : CSLOPE * y1;
                    mx1 = fmaxf(mx1, y1); sm1 += y1;
                }
            }
            #pragma unroll
            for (int off = 1; off <= 2; off <<= 1) {
                mx0 = fmaxf(mx0, __shfl_xor_sync(0xffffffffu, mx0, off));
                sm0 += __shfl_xor_sync(0xffffffffu, sm0, off);
                mx1 = fmaxf(mx1, __shfl_xor_sync(0xffffffffu, mx1, off));
                sm1 += __shfl_xor_sync(0xffffffffu, sm1, off);
            }
            if (qc == 0) {
                smax[rl][wn] = mx0; ssum[rl][wn] = sm0;
                smax[rl + 8][wn] = mx1; ssum[rl + 8][wn] = sm1;
            }
        }
        __syncthreads();
        if (tid < 128) {
            float mx = -INFINITY, sm = 0.f;
            #pragma unroll
            for (int w = 0; w < 4; w++) { mx = fmaxf(mx, smax[tid][w]); sm += ssum[tid][w]; }
            size_t o = (size_t)z * NPTS + m0 + tid;
            g_pmax[o * 8 + blockIdx.x] = mx;
            g_psum[o * 8 + blockIdx.x] = sm;
        }
    }
}

// ================= top-20 selection (lane-cached local max) =================
__device__ __forceinline__ void select20(float d[32], int lane, int* myidx) {
    float lm = -INFINITY; int lj = 0;
    #pragma unroll
    for (int j = 0; j < 32; j++) if (d[j] > lm) { lm = d[j]; lj = j; }
    for (int k = 0; k < KNB; k++) {
        float bv = lm; int bidx = lj * 32 + lane;
        #pragma unroll
        for (int off = 16; off > 0; off >>= 1) {
            float ov = __shfl_xor_sync(0xffffffffu, bv, off);
            int   oi = __shfl_xor_sync(0xffffffffu, bidx, off);
            if (ov > bv || (ov == bv && oi < bidx)) { bv = ov; bidx = oi; }
        }
        if (lane == (bidx & 31)) {
            int jj = bidx >> 5;
            lm = -INFINITY; lj = 0;
            #pragma unroll
            for (int j = 0; j < 32; j++) {
                if (j == jj) d[j] = -INFINITY;
                if (d[j] > lm) { lm = d[j]; lj = j; }
            }
        }
        if (lane == 0) myidx[k] = bidx;
    }
}

__global__ void __launch_bounds__(256) topk_kernel() {
    const int tid = threadIdx.x, lane = tid & 31;
    const int gw = blockIdx.x * 8 + (tid >> 5);
    const int b = gw >> 10, n = gw & 1023;
    const float* Grow = g_gram + ((size_t)b * NPTS + n) * NPTS;
    const float* xxb = g_xx + b * NPTS;
    float d[32];
    #pragma unroll
    for (int j = 0; j < 32; j++) {
        int m = j * 32 + lane;
        d[j] = 2.f * Grow[m] - xxb[m];
    }
    select20(d, lane, g_idx + ((size_t)b * NPTS + n) * KNB);
}

// block-1 topk (C=3 inline, exact fp32) + all weight prep folded in
__global__ void __launch_bounds__(256) topk3_prep_kernel(
    const float* __restrict__ x,
    const float* __restrict__ w0, const float* __restrict__ w1,
    const float* __restrict__ w2, const float* __restrict__ w3,
    const float* __restrict__ we)
{
    const int tid = threadIdx.x, lane = tid & 31;
    const int gw = blockIdx.x * 8 + (tid >> 5);
    const int b = gw >> 10, n = gw & 1023;
    const float* xb = x + (size_t)b * 3 * NPTS;
    float c0 = xb[n], c1 = xb[NPTS + n], c2 = xb[2 * NPTS + n];
    float d[32];
    #pragma unroll
    for (int j = 0; j < 32; j++) {
        int m = j * 32 + lane;
        float v0 = xb[m], v1 = xb[NPTS + m], v2 = xb[2 * NPTS + m];
        float dot = fmaf(v2, c2, fmaf(v1, c1, fmaf(v0, c0, 0.f)));
        float xxm = fmaf(v2, v2, fmaf(v1, v1, fmaf(v0, v0, 0.f)));
        d[j] = 2.f * dot - xxm;
    }
    select20(d, lane, g_idx + ((size_t)b * NPTS + n) * KNB);

    // conv weight packing [kp][2O] per segment
    for (int i = blockIdx.x * 256 + tid; i < WTOT; i += 1024 * 256) {
        const float* w; int C, O, loc;
        if (i < WOFF1)      { w = w0; C = 3;   O = 64;  loc = i - WOFF0; }
        else if (i < WOFF2) { w = w1; C = 64;  O = 64;  loc = i - WOFF1; }
        else if (i < WOFF3) { w = w2; C = 64;  O = 128; loc = i - WOFF2; }
        else                { w = w3; C = 128; O = 256; loc = i - WOFF3; }
        int N2 = 2 * O, kp = loc / N2, j = loc - kp * N2;
        float v;
        if (j < O) v = w[(size_t)j * 2 * C + kp];
        else { int o = j - O; v = w[(size_t)o * 2 * C + C + kp] - w[(size_t)o * 2 * C + kp]; }
        g_Wt[i] = v;
    }
    // we transpose to K-major [c][o]
    for (int i = blockIdx.x * 256 + tid; i < 512 * 1024; i += 1024 * 256) {
        int c = i >> 10, o = i & 1023;
        g_weT[i] = we[(size_t)o * 512 + c];
    }
}

// ================= conv epilogue (+ optional xx of the written layer) =================
template<int O, bool WX>
__global__ void __launch_bounds__(O) cepi_kernel(const float* __restrict__ bnp, int cout_off) {
    const int b = blockIdx.y, n = blockIdx.x, o = threadIdx.x;
    const int lane = o & 31, wid = o >> 5;
    __shared__ int jid[KNB];
    if (o < KNB) jid[o] = g_idx[((size_t)b * NPTS + n) * KNB + o];
    __syncthreads();
    const int ld = 2 * O;
    const size_t rowbase = (size_t)b * NPTS;
    float mx = -INFINITY;
    #pragma unroll 4
    for (int k = 0; k < KNB; k++)
        mx = fmaxf(mx, g_Z[(rowbase + jid[k]) * ld + o]);
    mx += g_Z[(rowbase + n) * ld + O + o];
    float gg = bnp[o], bb = bnp[O + o], mm = bnp[2 * O + o], vv = bnp[3 * O + o];
    float scale = gg / sqrtf(vv + CEPS);
    float y = (mx - mm) * scale + bb;
    y = (y > 0.f) ? y : CSLOPE * y;
    g_cat[(size_t)b * 512 * NPTS + (size_t)(cout_off + o) * NPTS + n] = y;
    if (WX) {
        float s = y * y;
        #pragma unroll
        for (int off = 16; off > 0; off >>= 1) s += __shfl_xor_sync(0xffffffffu, s, off);
        __shared__ float ws[O / 32];
        if (lane == 0) ws[wid] = s;
        __syncthreads();
        if (o == 0) {
            float t = 0.f;
            #pragma unroll
            for (int w = 0; w < O / 32; w++) t += ws[w];
            g_xx[b * NPTS + n] = t;
        }
    }
}

// ================= fused MLP head =================
__global__ void __launch_bounds__(512) head_kernel(
    const float* __restrict__ wf0, const float* __restrict__ bnf0,
    const float* __restrict__ wf1, const float* __restrict__ bnf1,
    const float* __restrict__ wfin, const float* __restrict__ bfin,
    float* __restrict__ out)
{
    const int b = blockIdx.x, tid = threadIdx.x;
    __shared__ float h0s[2048];
    __shared__ float h1s[512];
    __shared__ float h2s[256];

    // finish embed pools
    for (int o = tid; o < 1024; o += 512) {
        size_t base = ((size_t)b * NPTS + o) * 8;
        float mx = -INFINITY, sm = 0.f;
        #pragma unroll
        for (int t = 0; t < 8; t++) { mx = fmaxf(mx, g_pmax[base + t]); sm += g_psum[base + t]; }
        h0s[o] = mx;
        h0s[1024 + o] = sm * (1.0f / 1024.0f);
        g_h0[b * 2048 + o] = mx;                  // keep for determinism/debug
        g_h0[b * 2048 + 1024 + o] = sm * (1.0f / 1024.0f);
    }
    __syncthreads();

    {   // h1 = lrelu(bn(h0 @ wf0^T))
        const int o = tid;
        const float* wr = wf0 + (size_t)o * 2048;
        float a0 = 0.f, a1 = 0.f, a2 = 0.f, a3 = 0.f;
        for (int c = 0; c < 2048; c += 4) {
            a0 = fmaf(h0s[c],     wr[c],     a0);
            a1 = fmaf(h0s[c + 1], wr[c + 1], a1);
            a2 = fmaf(h0s[c + 2], wr[c + 2], a2);
            a3 = fmaf(h0s[c + 3], wr[c + 3], a3);
        }
        float acc = (a0 + a1) + (a2 + a3);
        float scale = bnf0[o] / sqrtf(bnf0[1536 + o] + CEPS);
        float y = (acc - bnf0[1024 + o]) * scale + bnf0[512 + o];
        h1s[o] = (y > 0.f) ? y : CSLOPE * y;
    }
    __syncthreads();

    if (tid < 256) {   // h2
        const int o = tid;
        const float* wr = wf1 + (size_t)o * 512;
        float a0 = 0.f, a1 = 0.f, a2 = 0.f, a3 = 0.f;
        for (int c = 0; c < 512; c += 4) {
            a0 = fmaf(h1s[c],     wr[c],     a0);
            a1 = fmaf(h1s[c + 1], wr[c + 1], a1);
            a2 = fmaf(h1s[c + 2], wr[c + 2], a2);
            a3 = fmaf(h1s[c + 3], wr[c + 3], a3);
        }
        float acc = (a0 + a1) + (a2 + a3);
        float scale = bnf1[o] / sqrtf(bnf1[768 + o] + CEPS);
        float y = (acc - bnf1[512 + o]) * scale + bnf1[256 + o];
        h2s[o] = (y > 0.f) ? y : CSLOPE * y;
    }
    __syncthreads();

    if (tid < 64) {   // final
        const int o = tid;
        const float* wr = wfin + (size_t)o * 256;
        float a0 = 0.f, a1 = 0.f, a2 = 0.f, a3 = 0.f;
        for (int c = 0; c < 256; c += 4) {
            a0 = fmaf(h2s[c],     wr[c],     a0);
            a1 = fmaf(h2s[c + 1], wr[c + 1], a1);
            a2 = fmaf(h2s[c + 2], wr[c + 2], a2);
            a3 = fmaf(h2s[c + 3], wr[c + 3], a3);
        }
        out[b * 64 + o] = bfin[o] + (a0 + a1) + (a2 + a3);
    }
}

// ================= launch =================
extern "C" void kernel_launch(void* const* d_in, const int* in_sizes, int n_in,
                              void* d_out, int out_size) {
    const float* x    = (const float*)d_in[0];
    const float* w0   = (const float*)d_in[1];
    const float* w1   = (const float*)d_in[2];
    const float* w2   = (const float*)d_in[3];
    const float* w3   = (const float*)d_in[4];
    const float* bn0  = (const float*)d_in[5];
    const float* bn1  = (const float*)d_in[6];
    const float* bn2  = (const float*)d_in[7];
    const float* bn3  = (const float*)d_in[8];
    const float* we   = (const float*)d_in[9];
    const float* bne  = (const float*)d_in[10];
    const float* wf0  = (const float*)d_in[11];
    const float* bnf0 = (const float*)d_in[12];
    const float* wf1  = (const float*)d_in[13];
    const float* bnf1 = (const float*)d_in[14];
    const float* wfin = (const float*)d_in[15];
    const float* bfin = (const float*)d_in[16];

    float *Zp, *Wtp, *catp, *gramp, *weTp;
    cudaGetSymbolAddress((void**)&Zp, g_Z);
    cudaGetSymbolAddress((void**)&Wtp, g_Wt);
    cudaGetSymbolAddress((void**)&catp, g_cat);
    cudaGetSymbolAddress((void**)&gramp, g_gram);
    cudaGetSymbolAddress((void**)&weTp, g_weT);

    dim3 gpn(NPTS, BATCH);
    const size_t sCat = (size_t)512 * NPTS;
    const size_t sG = (size_t)NPTS * NPTS;

    // ---- block 1: x (C=3) -> x1 (64) at cat[0:64] ----
    topk3_prep_kernel<<<1024, 256>>>(x, w0, w1, w2, w3, we);
    gemm16<false><<<dim3(1, 8, BATCH), 256>>>(x, Wtp + WOFF0, Zp, nullptr, 3,
                                              NPTS, 128, 128, (size_t)3 * NPTS, 0, (size_t)NPTS * 128);
    cepi_kernel<64, true><<<gpn, 64>>>(bn0, 0);

    // ---- block 2: x1 -> x2 (64) at cat[64:128] ----
    gemm16<false><<<dim3(8, 8, BATCH), 256>>>(catp, catp, gramp, nullptr, 64,
                                              NPTS, NPTS, NPTS, sCat, sCat, sG);
    topk_kernel<<<1024, 256>>>();
    gemm16<false><<<dim3(1, 8, BATCH), 256>>>(catp, Wtp + WOFF1, Zp, nullptr, 64,
                                              NPTS, 128, 128, sCat, 0, (size_t)NPTS * 128);
    cepi_kernel<64, true><<<gpn, 64>>>(bn1, 64);

    // ---- block 3: x2 -> x3 (128) at cat[128:256] ----
    gemm16<false><<<dim3(8, 8, BATCH), 256>>>(catp + (size_t)64 * NPTS, catp + (size_t)64 * NPTS,
                                              gramp, nullptr, 64, NPTS, NPTS, NPTS, sCat, sCat, sG);
    topk_kernel<<<1024, 256>>>();
    gemm16<false><<<dim3(2, 8, BATCH), 256>>>(catp + (size_t)64 * NPTS, Wtp + WOFF2, Zp, nullptr, 64,
                                              NPTS, 256, 256, sCat, 0, (size_t)NPTS * 256);
    cepi_kernel<128, true><<<gpn, 128>>>(bn2, 128);

    // ---- block 4: x3 -> x4 (256) at cat[256:512] ----
    gemm16<false><<<dim3(8, 8, BATCH), 256>>>(catp + (size_t)128 * NPTS, catp + (size_t)128 * NPTS,
                                              gramp, nullptr, 128, NPTS, NPTS, NPTS, sCat, sCat, sG);
    topk_kernel<<<1024, 256>>>();
    gemm16<false><<<dim3(4, 8, BATCH), 256>>>(catp + (size_t)128 * NPTS, Wtp + WOFF3, Zp, nullptr, 128,
                                              NPTS, 512, 512, sCat, 0, (size_t)NPTS * 512);
    cepi_kernel<256, false><<<gpn, 256>>>(bn3, 256);

    // ---- embedding GEMM (weT K-major) with fused BN+lrelu+pool partials ----
    gemm16<true><<<dim3(8, 8, BATCH), 256>>>(weTp, catp, nullptr, bne, 512,
                                             1024, NPTS, 0, 0, sCat, 0);

    // ---- fused MLP head ----
    head_kernel<<<BATCH, 512>>>(wf0, bnf0, wf1, bnf1, wfin, bfin, (float*)d_out);
}

// round 9
// speedup vs baseline: 1.2197x; 1.0421x over previous
#include <cuda_runtime.h>
#include <cuda_fp16.h>
#include <math.h>
#include <stdint.h>

#define NPTS 1024
#define KNB 20
#define BATCH 8
#define CEPS 1e-5f
#define CSLOPE 0.2f

// ---------------- scratch (no allocations allowed) ----------------
// activations pre-split into half hi/lo, k-pair interleaved: [b][c>>1][n][c&1]
__device__ __half   g_catH[(size_t)BATCH * 256 * NPTS * 2];
__device__ __half   g_catL[(size_t)BATCH * 256 * NPTS * 2];
__device__ float    g_gram[(size_t)BATCH * NPTS * NPTS];
__device__ float    g_xx[BATCH * NPTS];
__device__ int      g_idx[(size_t)BATCH * NPTS * KNB];
__device__ float    g_Z[(size_t)BATCH * NPTS * 512];
// packed conv weights, pair-interleaved uint32 (half2), 4 segments
__device__ uint32_t g_WtH[45312], g_WtL[45312];
__device__ uint32_t g_weTH[256 * 1024], g_weTL[256 * 1024];   // we K-major pairs [c>>1][o]
__device__ uint32_t g_xH[BATCH * 2 * NPTS], g_xL[BATCH * 2 * NPTS]; // input x pairs
__device__ float    g_pmax[BATCH * NPTS * 8];
__device__ float    g_psum[BATCH * NPTS * 8];

// Wt segment offsets in uint32: seg sizes 2*128, 32*128, 32*256, 64*512
#define WSEG0 0
#define WSEG1 256
#define WSEG2 4352
#define WSEG3 12544
#define WTOTU 45312

// ================= helpers =================
__device__ __forceinline__ uint32_t packh(float a, float b) {
    __half2 h = __halves2half2(__float2half_rn(a), __float2half_rn(b));
    return *(uint32_t*)&h;
}
__device__ __forceinline__ uint32_t packl(float a, float b) {
    float ra = a - __half2float(__float2half_rn(a));
    float rb = b - __half2float(__float2half_rn(b));
    __half2 h = __halves2half2(__float2half_rn(ra), __float2half_rn(rb));
    return *(uint32_t*)&h;
}
__device__ __forceinline__ void mma16(float* c, const uint32_t* a, const uint32_t* b) {
    asm volatile(
        "mma.sync.aligned.m16n8k16.row.col.f32.f16.f16.f32 "
        "{%0,%1,%2,%3}, {%4,%5,%6,%7}, {%8,%9}, {%0,%1,%2,%3};\n"
        : "+f"(c[0]), "+f"(c[1]), "+f"(c[2]), "+f"(c[3])
        : "r"(a[0]), "r"(a[1]), "r"(a[2]), "r"(a[3]), "r"(b[0]), "r"(b[1]));
}

// stage one [16 kp][128 col] uint32 tile: pure copy, zero-fill beyond rows_left
__device__ __forceinline__ void stageu(const uint32_t* __restrict__ src, int ld,
                                       int rows_left, int tid, uint32_t (*S)[136]) {
    #pragma unroll
    for (int i = 0; i < 2; i++) {
        int lin = tid + i * 256;
        int r = lin >> 5, c4 = (lin & 31) * 4;
        uint4 v = make_uint4(0u, 0u, 0u, 0u);
        if (r < rows_left) v = *(const uint4*)(src + (size_t)r * ld + c4);
        *(uint4*)&S[r][c4] = v;
    }
}

// ================= fp16-split GEMM on pre-split operands =================
// C[m][n] = sum_k A[k][m]*B[k][n], operands given as hi/lo half2-pair uint32 arrays.
// KP = number of k-pairs. 128x128 tile, 8 warps.
template<bool POOL>
__global__ void __launch_bounds__(256) gemm16(
    const uint32_t* __restrict__ Ahg, const uint32_t* __restrict__ Alg,
    const uint32_t* __restrict__ Bhg, const uint32_t* __restrict__ Blg,
    float* __restrict__ Cc, const float* __restrict__ bne,
    int KP, int lda, int ldb, int ldc, size_t sAz, size_t sBz, size_t sCz)
{
    const int z = blockIdx.z;
    const int m0 = blockIdx.y * 128, n0 = blockIdx.x * 128;
    const uint32_t* Abh = Ahg + z * sAz + m0;
    const uint32_t* Abl = Alg + z * sAz + m0;
    const uint32_t* Bbh = Bhg + z * sBz + n0;
    const uint32_t* Bbl = Blg + z * sBz + n0;

    __shared__ uint32_t Ah[16][136], Al[16][136], Bh[16][136], Bl[16][136];

    const int tid = threadIdx.x, lane = tid & 31, wrp = tid >> 5;
    const int wm = wrp >> 2, wn = wrp & 3;
    const int qr = lane >> 2, qc = lane & 3;

    float acc[4][4][4];
    #pragma unroll
    for (int i = 0; i < 4; i++)
        #pragma unroll
        for (int j = 0; j < 4; j++)
            #pragma unroll
            for (int q = 0; q < 4; q++) acc[i][j][q] = 0.f;

    const int KT = (KP + 15) / 16;
    for (int kt = 0; kt < KT; kt++) {
        int rl = KP - kt * 16;
        stageu(Abh + (size_t)kt * 16 * lda, lda, rl, tid, Ah);
        stageu(Abl + (size_t)kt * 16 * lda, lda, rl, tid, Al);
        stageu(Bbh + (size_t)kt * 16 * ldb, ldb, rl, tid, Bh);
        stageu(Bbl + (size_t)kt * 16 * ldb, ldb, rl, tid, Bl);
        __syncthreads();
        #pragma unroll
        for (int kk = 0; kk < 2; kk++) {
            const int kb = kk * 8;
            uint32_t ah[4][4], al[4][4], bh[4][2], bl[4][2];
            #pragma unroll
            for (int mt = 0; mt < 4; mt++) {
                int R = wm * 64 + mt * 16;
                ah[mt][0] = Ah[kb + qc][R + qr];     ah[mt][1] = Ah[kb + qc][R + qr + 8];
                ah[mt][2] = Ah[kb + qc + 4][R + qr]; ah[mt][3] = Ah[kb + qc + 4][R + qr + 8];
                al[mt][0] = Al[kb + qc][R + qr];     al[mt][1] = Al[kb + qc][R + qr + 8];
                al[mt][2] = Al[kb + qc + 4][R + qr]; al[mt][3] = Al[kb + qc + 4][R + qr + 8];
            }
            #pragma unroll
            for (int nt = 0; nt < 4; nt++) {
                int C0 = wn * 32 + nt * 8;
                bh[nt][0] = Bh[kb + qc][C0 + qr]; bh[nt][1] = Bh[kb + qc + 4][C0 + qr];
                bl[nt][0] = Bl[kb + qc][C0 + qr]; bl[nt][1] = Bl[kb + qc + 4][C0 + qr];
            }
            #pragma unroll
            for (int mt = 0; mt < 4; mt++)
                #pragma unroll
                for (int nt = 0; nt < 4; nt++) {
                    mma16(acc[mt][nt], ah[mt], bh[nt]);
                    mma16(acc[mt][nt], al[mt], bh[nt]);
                    mma16(acc[mt][nt], ah[mt], bl[nt]);
                }
        }
        __syncthreads();
    }

    if (!POOL) {
        float* Cb = Cc + z * sCz;
        #pragma unroll
        for (int mt = 0; mt < 4; mt++)
            #pragma unroll
            for (int nt = 0; nt < 4; nt++) {
                int r = m0 + wm * 64 + mt * 16 + qr;
                int cc = n0 + wn * 32 + nt * 8 + 2 * qc;
                *(float2*)(Cb + (size_t)r * ldc + cc)       = make_float2(acc[mt][nt][0], acc[mt][nt][1]);
                *(float2*)(Cb + (size_t)(r + 8) * ldc + cc) = make_float2(acc[mt][nt][2], acc[mt][nt][3]);
            }
    } else {
        __shared__ float smax[128][5], ssum[128][5];
        #pragma unroll
        for (int mt = 0; mt < 4; mt++) {
            int rl2 = wm * 64 + mt * 16 + qr;
            int o0 = m0 + rl2, o1 = o0 + 8;
            float s0 = bne[o0] / sqrtf(bne[3072 + o0] + CEPS);
            float b0 = bne[1024 + o0], u0 = bne[2048 + o0];
            float s1 = bne[o1] / sqrtf(bne[3072 + o1] + CEPS);
            float b1 = bne[1024 + o1], u1 = bne[2048 + o1];
            float mx0 = -INFINITY, sm0 = 0.f, mx1 = -INFINITY, sm1 = 0.f;
            #pragma unroll
            for (int nt = 0; nt < 4; nt++) {
                #pragma unroll
                for (int p = 0; p < 2; p++) {
                    float y0 = (acc[mt][nt][p] - u0) * s0 + b0;
                    y0 = (y0 > 0.f) ? y0 : CSLOPE * y0;
                    mx0 = fmaxf(mx0, y0); sm0 += y0;
                    float y1 = (acc[mt][nt][2 + p] - u1) * s1 + b1;
                    y1 = (y1 > 0.f) ? y1 : CSLOPE * y1;
                    mx1 = fmaxf(mx1, y1); sm1 += y1;
                }
            }
            #pragma unroll
            for (int off = 1; off <= 2; off <<= 1) {
                mx0 = fmaxf(mx0, __shfl_xor_sync(0xffffffffu, mx0, off));
                sm0 += __shfl_xor_sync(0xffffffffu, sm0, off);
                mx1 = fmaxf(mx1, __shfl_xor_sync(0xffffffffu, mx1, off));
                sm1 += __shfl_xor_sync(0xffffffffu, sm1, off);
            }
            if (qc == 0) {
                smax[rl2][wn] = mx0; ssum[rl2][wn] = sm0;
                smax[rl2 + 8][wn] = mx1; ssum[rl2 + 8][wn] = sm1;
            }
        }
        __syncthreads();
        if (tid < 128) {
            float mx = -INFINITY, sm = 0.f;
            #pragma unroll
            for (int w = 0; w < 4; w++) { mx = fmaxf(mx, smax[tid][w]); sm += ssum[tid][w]; }
            size_t o = (size_t)z * NPTS + m0 + tid;
            g_pmax[o * 8 + blockIdx.x] = mx;
            g_psum[o * 8 + blockIdx.x] = sm;
        }
    }
}

// ================= top-20 selection =================
__device__ __forceinline__ void select20(float d[32], int lane, int* myidx) {
    float lm = -INFINITY; int lj = 0;
    #pragma unroll
    for (int j = 0; j < 32; j++) if (d[j] > lm) { lm = d[j]; lj = j; }
    for (int k = 0; k < KNB; k++) {
        float bv = lm; int bidx = lj * 32 + lane;
        #pragma unroll
        for (int off = 16; off > 0; off >>= 1) {
            float ov = __shfl_xor_sync(0xffffffffu, bv, off);
            int   oi = __shfl_xor_sync(0xffffffffu, bidx, off);
            if (ov > bv || (ov == bv && oi < bidx)) { bv = ov; bidx = oi; }
        }
        if (lane == (bidx & 31)) {
            int jj = bidx >> 5;
            lm = -INFINITY; lj = 0;
            #pragma unroll
            for (int j = 0; j < 32; j++) {
                if (j == jj) d[j] = -INFINITY;
                if (d[j] > lm) { lm = d[j]; lj = j; }
            }
        }
        if (lane == 0) myidx[k] = bidx;
    }
}

__global__ void __launch_bounds__(256) topk_kernel() {
    const int tid = threadIdx.x, lane = tid & 31;
    const int gw = blockIdx.x * 8 + (tid >> 5);
    const int b = gw >> 10, n = gw & 1023;
    const float* Grow = g_gram + ((size_t)b * NPTS + n) * NPTS;
    const float* xxb = g_xx + b * NPTS;
    float d[32];
    #pragma unroll
    for (int j = 0; j < 32; j++) {
        int m = j * 32 + lane;
        d[j] = 2.f * Grow[m] - xxb[m];
    }
    select20(d, lane, g_idx + ((size_t)b * NPTS + n) * KNB);
}

// block-1 topk (C=3 inline exact fp32) + ALL weight/input pre-split packing
__global__ void __launch_bounds__(256) topk3_prep_kernel(
    const float* __restrict__ x,
    const float* __restrict__ w0, const float* __restrict__ w1,
    const float* __restrict__ w2, const float* __restrict__ w3,
    const float* __restrict__ we)
{
    const int tid = threadIdx.x, lane = tid & 31;
    const int gw = blockIdx.x * 8 + (tid >> 5);
    const int b = gw >> 10, n = gw & 1023;
    const float* xb = x + (size_t)b * 3 * NPTS;
    float c0 = xb[n], c1 = xb[NPTS + n], c2 = xb[2 * NPTS + n];
    float d[32];
    #pragma unroll
    for (int j = 0; j < 32; j++) {
        int m = j * 32 + lane;
        float v0 = xb[m], v1 = xb[NPTS + m], v2 = xb[2 * NPTS + m];
        float dot = fmaf(v2, c2, fmaf(v1, c1, fmaf(v0, c0, 0.f)));
        float xxm = fmaf(v2, v2, fmaf(v1, v1, fmaf(v0, v0, 0.f)));
        d[j] = 2.f * dot - xxm;
    }
    select20(d, lane, g_idx + ((size_t)b * NPTS + n) * KNB);

    const int gstride = 1024 * 256;
    int gid = blockIdx.x * 256 + tid;

    // x pairs: [b][2][n] - pair0=(x0,x1), pair1=(x2,0)
    for (int i = gid; i < BATCH * NPTS; i += gstride) {
        int bb = i >> 10, nn = i & 1023;
        const float* xr = x + (size_t)bb * 3 * NPTS;
        float v0 = xr[nn], v1 = xr[NPTS + nn], v2 = xr[2 * NPTS + nn];
        g_xH[(bb * 2 + 0) * NPTS + nn] = packh(v0, v1);
        g_xL[(bb * 2 + 0) * NPTS + nn] = packl(v0, v1);
        g_xH[(bb * 2 + 1) * NPTS + nn] = packh(v2, 0.f);
        g_xL[(bb * 2 + 1) * NPTS + nn] = packl(v2, 0.f);
    }

    // conv weights: per segment, [p][j] packs k=2p,2p+1 at column j (j<O: W1, else Wd)
    for (int i = gid; i < WTOTU; i += gstride) {
        const float* w; int C, O, loc;
        if (i < WSEG1)      { w = w0; C = 3;   O = 64;  loc = i - WSEG0; }
        else if (i < WSEG2) { w = w1; C = 64;  O = 64;  loc = i - WSEG1; }
        else if (i < WSEG3) { w = w2; C = 64;  O = 128; loc = i - WSEG2; }
        else                { w = w3; C = 128; O = 256; loc = i - WSEG3; }
        int N2 = 2 * O, p = loc / N2, j = loc - p * N2;
        int k0 = 2 * p, k1 = 2 * p + 1;
        float v0, v1;
        if (j < O) {
            v0 = w[(size_t)j * 2 * C + k0];
            v1 = (k1 < C) ? w[(size_t)j * 2 * C + k1] : 0.f;
        } else {
            int o = j - O;
            v0 = w[(size_t)o * 2 * C + C + k0] - w[(size_t)o * 2 * C + k0];
            v1 = (k1 < C) ? (w[(size_t)o * 2 * C + C + k1] - w[(size_t)o * 2 * C + k1]) : 0.f;
        }
        g_WtH[i] = packh(v0, v1);
        g_WtL[i] = packl(v0, v1);
    }

    // we pairs: [p][o] packs c=2p, 2p+1
    for (int i = gid; i < 256 * 1024; i += gstride) {
        int p = i >> 10, o = i & 1023;
        float v0 = we[(size_t)o * 512 + 2 * p];
        float v1 = we[(size_t)o * 512 + 2 * p + 1];
        g_weTH[i] = packh(v0, v1);
        g_weTL[i] = packl(v0, v1);
    }
}

// ================= conv epilogue: pool-over-K + BN + lrelu, emit split halves =================
template<int O, bool WX>
__global__ void __launch_bounds__(O) cepi_kernel(const float* __restrict__ bnp, int cout_off) {
    const int b = blockIdx.y, n = blockIdx.x, o = threadIdx.x;
    const int lane = o & 31, wid = o >> 5;
    __shared__ int jid[KNB];
    if (o < KNB) jid[o] = g_idx[((size_t)b * NPTS + n) * KNB + o];
    __syncthreads();
    const int ld = 2 * O;
    const size_t rowbase = (size_t)b * NPTS;
    float mx = -INFINITY;
    #pragma unroll 4
    for (int k = 0; k < KNB; k++)
        mx = fmaxf(mx, g_Z[(rowbase + jid[k]) * ld + o]);
    mx += g_Z[(rowbase + n) * ld + O + o];
    float gg = bnp[o], bb = bnp[O + o], mm = bnp[2 * O + o], vv = bnp[3 * O + o];
    float scale = gg / sqrtf(vv + CEPS);
    float y = (mx - mm) * scale + bb;
    y = (y > 0.f) ? y : CSLOPE * y;

    int c = cout_off + o;
    size_t hidx = (((size_t)b * 256 + (c >> 1)) * NPTS + n) * 2 + (c & 1);
    __half hh = __float2half_rn(y);
    g_catH[hidx] = hh;
    g_catL[hidx] = __float2half_rn(y - __half2float(hh));

    if (WX) {
        float s = y * y;
        #pragma unroll
        for (int off = 16; off > 0; off >>= 1) s += __shfl_xor_sync(0xffffffffu, s, off);
        __shared__ float ws[O / 32];
        if (lane == 0) ws[wid] = s;
        __syncthreads();
        if (o == 0) {
            float t = 0.f;
            #pragma unroll
            for (int w = 0; w < O / 32; w++) t += ws[w];
            g_xx[b * NPTS + n] = t;
        }
    }
}

// ================= fused MLP head =================
__global__ void __launch_bounds__(512) head_kernel(
    const float* __restrict__ wf0, const float* __restrict__ bnf0,
    const float* __restrict__ wf1, const float* __restrict__ bnf1,
    const float* __restrict__ wfin, const float* __restrict__ bfin,
    float* __restrict__ out)
{
    const int b = blockIdx.x, tid = threadIdx.x;
    __shared__ float h0s[2048];
    __shared__ float h1s[512];
    __shared__ float h2s[256];

    for (int o = tid; o < 1024; o += 512) {
        size_t base = ((size_t)b * NPTS + o) * 8;
        float mx = -INFINITY, sm = 0.f;
        #pragma unroll
        for (int t = 0; t < 8; t++) { mx = fmaxf(mx, g_pmax[base + t]); sm += g_psum[base + t]; }
        h0s[o] = mx;
        h0s[1024 + o] = sm * (1.0f / 1024.0f);
    }
    __syncthreads();

    {
        const int o = tid;
        const float* wr = wf0 + (size_t)o * 2048;
        float a0 = 0.f, a1 = 0.f, a2 = 0.f, a3 = 0.f;
        for (int c = 0; c < 2048; c += 4) {
            a0 = fmaf(h0s[c],     wr[c],     a0);
            a1 = fmaf(h0s[c + 1], wr[c + 1], a1);
            a2 = fmaf(h0s[c + 2], wr[c + 2], a2);
            a3 = fmaf(h0s[c + 3], wr[c + 3], a3);
        }
        float acc = (a0 + a1) + (a2 + a3);
        float scale = bnf0[o] / sqrtf(bnf0[1536 + o] + CEPS);
        float y = (acc - bnf0[1024 + o]) * scale + bnf0[512 + o];
        h1s[o] = (y > 0.f) ? y : CSLOPE * y;
    }
    __syncthreads();

    if (tid < 256) {
        const int o = tid;
        const float* wr = wf1 + (size_t)o * 512;
        float a0 = 0.f, a1 = 0.f, a2 = 0.f, a3 = 0.f;
        for (int c = 0; c < 512; c += 4) {
            a0 = fmaf(h1s[c],     wr[c],     a0);
            a1 = fmaf(h1s[c + 1], wr[c + 1], a1);
            a2 = fmaf(h1s[c + 2], wr[c + 2], a2);
            a3 = fmaf(h1s[c + 3], wr[c + 3], a3);
        }
        float acc = (a0 + a1) + (a2 + a3);
        float scale = bnf1[o] / sqrtf(bnf1[768 + o] + CEPS);
        float y = (acc - bnf1[512 + o]) * scale + bnf1[256 + o];
        h2s[o] = (y > 0.f) ? y : CSLOPE * y;
    }
    __syncthreads();

    if (tid < 64) {
        const int o = tid;
        const float* wr = wfin + (size_t)o * 256;
        float a0 = 0.f, a1 = 0.f, a2 = 0.f, a3 = 0.f;
        for (int c = 0; c < 256; c += 4) {
            a0 = fmaf(h2s[c],     wr[c],     a0);
            a1 = fmaf(h2s[c + 1], wr[c + 1], a1);
            a2 = fmaf(h2s[c + 2], wr[c + 2], a2);
            a3 = fmaf(h2s[c + 3], wr[c + 3], a3);
        }
        out[b * 64 + o] = bfin[o] + (a0 + a1) + (a2 + a3);
    }
}

// ================= launch =================
extern "C" void kernel_launch(void* const* d_in, const int* in_sizes, int n_in,
                              void* d_out, int out_size) {
    const float* x    = (const float*)d_in[0];
    const float* w0   = (const float*)d_in[1];
    const float* w1   = (const float*)d_in[2];
    const float* w2   = (const float*)d_in[3];
    const float* w3   = (const float*)d_in[4];
    const float* bn0  = (const float*)d_in[5];
    const float* bn1  = (const float*)d_in[6];
    const float* bn2  = (const float*)d_in[7];
    const float* bn3  = (const float*)d_in[8];
    const float* we   = (const float*)d_in[9];
    const float* bne  = (const float*)d_in[10];
    const float* wf0  = (const float*)d_in[11];
    const float* bnf0 = (const float*)d_in[12];
    const float* wf1  = (const float*)d_in[13];
    const float* bnf1 = (const float*)d_in[14];
    const float* wfin = (const float*)d_in[15];
    const float* bfin = (const float*)d_in[16];

    float *Zp, *gramp;
    uint32_t *catHp, *catLp, *WtHp, *WtLp, *weTHp, *weTLp, *xHp, *xLp;
    cudaGetSymbolAddress((void**)&Zp, g_Z);
    cudaGetSymbolAddress((void**)&gramp, g_gram);
    cudaGetSymbolAddress((void**)&catHp, g_catH);
    cudaGetSymbolAddress((void**)&catLp, g_catL);
    cudaGetSymbolAddress((void**)&WtHp, g_WtH);
    cudaGetSymbolAddress((void**)&WtLp, g_WtL);
    cudaGetSymbolAddress((void**)&weTHp, g_weTH);
    cudaGetSymbolAddress((void**)&weTLp, g_weTL);
    cudaGetSymbolAddress((void**)&xHp, g_xH);
    cudaGetSymbolAddress((void**)&xLp, g_xL);

    dim3 gpn(NPTS, BATCH);
    const size_t sCat = (size_t)256 * NPTS;     // uint32 stride per batch in catH/catL
    const size_t sG = (size_t)NPTS * NPTS;

    // ---- block 1: x (C=3) -> x1 (64) at channels [0:64) ----
    topk3_prep_kernel<<<1024, 256>>>(x, w0, w1, w2, w3, we);
    gemm16<false><<<dim3(1, 8, BATCH), 256>>>(xHp, xLp, WtHp + WSEG0, WtLp + WSEG0, Zp, nullptr,
                                              2, NPTS, 128, 128, (size_t)2 * NPTS, 0, (size_t)NPTS * 128);
    cepi_kernel<64, true><<<gpn, 64>>>(bn0, 0);

    // ---- block 2: x1 -> x2 (64) at [64:128) ----
    gemm16<false><<<dim3(8, 8, BATCH), 256>>>(catHp, catLp, catHp, catLp, gramp, nullptr,
                                              32, NPTS, NPTS, NPTS, sCat, sCat, sG);
    topk_kernel<<<1024, 256>>>();
    gemm16<false><<<dim3(1, 8, BATCH), 256>>>(catHp, catLp, WtHp + WSEG1, WtLp + WSEG1, Zp, nullptr,
                                              32, NPTS, 128, 128, sCat, 0, (size_t)NPTS * 128);
    cepi_kernel<64, true><<<gpn, 64>>>(bn1, 64);

    // ---- block 3: x2 -> x3 (128) at [128:256) ----
    gemm16<false><<<dim3(8, 8, BATCH), 256>>>(catHp + 32 * NPTS, catLp + 32 * NPTS,
                                              catHp + 32 * NPTS, catLp + 32 * NPTS, gramp, nullptr,
                                              32, NPTS, NPTS, NPTS, sCat, sCat, sG);
    topk_kernel<<<1024, 256>>>();
    gemm16<false><<<dim3(2, 8, BATCH), 256>>>(catHp + 32 * NPTS, catLp + 32 * NPTS,
                                              WtHp + WSEG2, WtLp + WSEG2, Zp, nullptr,
                                              32, NPTS, 256, 256, sCat, 0, (size_t)NPTS * 256);
    cepi_kernel<128, true><<<gpn, 128>>>(bn2, 128);

    // ---- block 4: x3 -> x4 (256) at [256:512) ----
    gemm16<false><<<dim3(8, 8, BATCH), 256>>>(catHp + 64 * NPTS, catLp + 64 * NPTS,
                                              catHp + 64 * NPTS, catLp + 64 * NPTS, gramp, nullptr,
                                              64, NPTS, NPTS, NPTS, sCat, sCat, sG);
    topk_kernel<<<1024, 256>>>();
    gemm16<false><<<dim3(4, 8, BATCH), 256>>>(catHp + 64 * NPTS, catLp + 64 * NPTS,
                                              WtHp + WSEG3, WtLp + WSEG3, Zp, nullptr,
                                              64, NPTS, 512, 512, sCat, 0, (size_t)NPTS * 512);
    cepi_kernel<256, false><<<gpn, 256>>>(bn3, 256);

    // ---- embedding GEMM with fused BN+lrelu+pool partials ----
    gemm16<true><<<dim3(8, 8, BATCH), 256>>>(weTHp, weTLp, catHp, catLp, nullptr, bne,
                                             256, NPTS, NPTS, 0, 0, sCat, 0);

    // ---- fused MLP head ----
    head_kernel<<<BATCH, 512>>>(wf0, bnf0, wf1, bnf1, wfin, bfin, (float*)d_out);
}

// round 10
// speedup vs baseline: 2.6674x; 2.1868x over previous
#include <cuda_runtime.h>
#include <cuda_fp16.h>
#include <math.h>
#include <stdint.h>

#define NPTS 1024
#define KNB 20
#define BATCH 8
#define CEPS 1e-5f
#define CSLOPE 0.2f

// ---------------- scratch (no allocations allowed) ----------------
__device__ __half   g_catH[(size_t)BATCH * 256 * NPTS * 2];
__device__ __half   g_catL[(size_t)BATCH * 256 * NPTS * 2];
__device__ float    g_gram[(size_t)BATCH * NPTS * NPTS];
__device__ float    g_xx[BATCH * NPTS];
__device__ int      g_idx[(size_t)BATCH * NPTS * KNB];
__device__ float    g_Z[(size_t)BATCH * NPTS * 512];
__device__ uint32_t g_WtH[45312], g_WtL[45312];
__device__ uint32_t g_weTH[256 * 1024], g_weTL[256 * 1024];
__device__ uint32_t g_xH[BATCH * 2 * NPTS], g_xL[BATCH * 2 * NPTS];
__device__ float    g_pmax[BATCH * NPTS * 8];
__device__ float    g_psum[BATCH * NPTS * 8];

#define WSEG0 0
#define WSEG1 256
#define WSEG2 4352
#define WSEG3 12544
#define WTOTU 45312

// ================= helpers =================
__device__ __forceinline__ uint32_t packh(float a, float b) {
    __half2 h = __halves2half2(__float2half_rn(a), __float2half_rn(b));
    return *(uint32_t*)&h;
}
__device__ __forceinline__ uint32_t packl(float a, float b) {
    float ra = a - __half2float(__float2half_rn(a));
    float rb = b - __half2float(__float2half_rn(b));
    __half2 h = __halves2half2(__float2half_rn(ra), __float2half_rn(rb));
    return *(uint32_t*)&h;
}
__device__ __forceinline__ void mma16(float* c, const uint32_t* a, const uint32_t* b) {
    asm volatile(
        "mma.sync.aligned.m16n8k16.row.col.f32.f16.f16.f32 "
        "{%0,%1,%2,%3}, {%4,%5,%6,%7}, {%8,%9}, {%0,%1,%2,%3};\n"
        : "+f"(c[0]), "+f"(c[1]), "+f"(c[2]), "+f"(c[3])
        : "r"(a[0]), "r"(a[1]), "r"(a[2]), "r"(a[3]), "r"(b[0]), "r"(b[1]));
}
__device__ __forceinline__ void cpa16(uint32_t s, const void* g, int ok) {
    asm volatile("cp.async.cg.shared.global [%0], [%1], 16, %2;"
                 :: "r"(s), "l"(g), "r"(ok ? 16 : 0));
}
__device__ __forceinline__ void cpa_commit() { asm volatile("cp.async.commit_group;"); }
template<int N> __device__ __forceinline__ void cpa_wait() {
    asm volatile("cp.async.wait_group %0;" :: "n"(N));
}

// ================= fp16-split GEMM, cp.async double-buffered =================
// C[m][n] = sum_k A[k][m]*B[k][n]; operands pre-split hi/lo half2-pair uint32 arrays.
// KP = k-pairs. 128x128 tile, 8 warps. Dynamic smem: 2 bufs x 4 arrays x 16x136 u32.
template<bool POOL>
__global__ void __launch_bounds__(256) gemm16(
    const uint32_t* __restrict__ Ahg, const uint32_t* __restrict__ Alg,
    const uint32_t* __restrict__ Bhg, const uint32_t* __restrict__ Blg,
    float* __restrict__ Cc, const float* __restrict__ bne,
    int KP, int lda, int ldb, int ldc, size_t sAz, size_t sBz, size_t sCz)
{
    extern __shared__ __align__(16) uint32_t smbuf[];
    const int z = blockIdx.z;
    const int m0 = blockIdx.y * 128, n0 = blockIdx.x * 128;
    const uint32_t* Abh = Ahg + z * sAz + m0;
    const uint32_t* Abl = Alg + z * sAz + m0;
    const uint32_t* Bbh = Bhg + z * sBz + n0;
    const uint32_t* Bbl = Blg + z * sBz + n0;

    const int tid = threadIdx.x, lane = tid & 31, wrp = tid >> 5;
    const int wm = wrp >> 2, wn = wrp & 3;
    const int qr = lane >> 2, qc = lane & 3;

    float acc[4][4][4];
    #pragma unroll
    for (int i = 0; i < 4; i++)
        #pragma unroll
        for (int j = 0; j < 4; j++)
            #pragma unroll
            for (int q = 0; q < 4; q++) acc[i][j][q] = 0.f;

    const int r0 = tid >> 5, c0 = (tid & 31) * 4;   // rows 0..7
    const int r1 = r0 + 8;                          // rows 8..15
    const uint32_t smbase = (uint32_t)__cvta_generic_to_shared(smbuf);
    const int KT = (KP + 15) / 16;

    auto issue = [&](int kt, int buf) {
        const int rl = KP - kt * 16;
        const size_t ko = (size_t)kt * 16;
        const uint32_t bb = smbase + (uint32_t)buf * (8704u * 4u);
        const uint32_t* pAh = Abh + ko * lda;
        const uint32_t* pAl = Abl + ko * lda;
        const uint32_t* pBh = Bbh + ko * ldb;
        const uint32_t* pBl = Bbl + ko * ldb;
        uint32_t d0 = bb + (uint32_t)(r0 * 136 + c0) * 4u;
        uint32_t d1 = bb + (uint32_t)(r1 * 136 + c0) * 4u;
        cpa16(d0,             pAh + (size_t)r0 * lda + c0, r0 < rl);
        cpa16(d1,             pAh + (size_t)r1 * lda + c0, r1 < rl);
        cpa16(d0 + 2176u * 4, pAl + (size_t)r0 * lda + c0, r0 < rl);
        cpa16(d1 + 2176u * 4, pAl + (size_t)r1 * lda + c0, r1 < rl);
        cpa16(d0 + 4352u * 4, pBh + (size_t)r0 * ldb + c0, r0 < rl);
        cpa16(d1 + 4352u * 4, pBh + (size_t)r1 * ldb + c0, r1 < rl);
        cpa16(d0 + 6528u * 4, pBl + (size_t)r0 * ldb + c0, r0 < rl);
        cpa16(d1 + 6528u * 4, pBl + (size_t)r1 * ldb + c0, r1 < rl);
        cpa_commit();
    };

    issue(0, 0);
    for (int kt = 0; kt < KT; kt++) {
        const int cur = kt & 1;
        if (kt + 1 < KT) { issue(kt + 1, cur ^ 1); cpa_wait<1>(); }
        else             { cpa_wait<0>(); }
        __syncthreads();
        const uint32_t* Ah = smbuf + cur * 8704;
        const uint32_t* Al = Ah + 2176;
        const uint32_t* Bh = Ah + 4352;
        const uint32_t* Bl = Ah + 6528;
        #pragma unroll
        for (int kk = 0; kk < 2; kk++) {
            const int kb = kk * 8;
            uint32_t ah[4][4], al[4][4], bh[4][2], bl[4][2];
            #pragma unroll
            for (int mt = 0; mt < 4; mt++) {
                int R = wm * 64 + mt * 16;
                ah[mt][0] = Ah[(kb + qc) * 136 + R + qr];
                ah[mt][1] = Ah[(kb + qc) * 136 + R + qr + 8];
                ah[mt][2] = Ah[(kb + qc + 4) * 136 + R + qr];
                ah[mt][3] = Ah[(kb + qc + 4) * 136 + R + qr + 8];
                al[mt][0] = Al[(kb + qc) * 136 + R + qr];
                al[mt][1] = Al[(kb + qc) * 136 + R + qr + 8];
                al[mt][2] = Al[(kb + qc + 4) * 136 + R + qr];
                al[mt][3] = Al[(kb + qc + 4) * 136 + R + qr + 8];
            }
            #pragma unroll
            for (int nt = 0; nt < 4; nt++) {
                int C0 = wn * 32 + nt * 8;
                bh[nt][0] = Bh[(kb + qc) * 136 + C0 + qr];
                bh[nt][1] = Bh[(kb + qc + 4) * 136 + C0 + qr];
                bl[nt][0] = Bl[(kb + qc) * 136 + C0 + qr];
                bl[nt][1] = Bl[(kb + qc + 4) * 136 + C0 + qr];
            }
            #pragma unroll
            for (int mt = 0; mt < 4; mt++)
                #pragma unroll
                for (int nt = 0; nt < 4; nt++) {
                    mma16(acc[mt][nt], ah[mt], bh[nt]);
                    mma16(acc[mt][nt], al[mt], bh[nt]);
                    mma16(acc[mt][nt], ah[mt], bl[nt]);
                }
        }
        __syncthreads();
    }

    if (!POOL) {
        float* Cb = Cc + z * sCz;
        #pragma unroll
        for (int mt = 0; mt < 4; mt++)
            #pragma unroll
            for (int nt = 0; nt < 4; nt++) {
                int r = m0 + wm * 64 + mt * 16 + qr;
                int cc = n0 + wn * 32 + nt * 8 + 2 * qc;
                *(float2*)(Cb + (size_t)r * ldc + cc)       = make_float2(acc[mt][nt][0], acc[mt][nt][1]);
                *(float2*)(Cb + (size_t)(r + 8) * ldc + cc) = make_float2(acc[mt][nt][2], acc[mt][nt][3]);
            }
    } else {
        __shared__ float smax[128][5], ssum[128][5];
        #pragma unroll
        for (int mt = 0; mt < 4; mt++) {
            int rl2 = wm * 64 + mt * 16 + qr;
            int o0 = m0 + rl2, o1 = o0 + 8;
            float s0 = bne[o0] / sqrtf(bne[3072 + o0] + CEPS);
            float b0 = bne[1024 + o0], u0 = bne[2048 + o0];
            float s1 = bne[o1] / sqrtf(bne[3072 + o1] + CEPS);
            float b1 = bne[1024 + o1], u1 = bne[2048 + o1];
            float mx0 = -INFINITY, sm0 = 0.f, mx1 = -INFINITY, sm1 = 0.f;
            #pragma unroll
            for (int nt = 0; nt < 4; nt++) {
                #pragma unroll
                for (int p = 0; p < 2; p++) {
                    float y0 = (acc[mt][nt][p] - u0) * s0 + b0;
                    y0 = (y0 > 0.f) ? y0 : CSLOPE * y0;
                    mx0 = fmaxf(mx0, y0); sm0 += y0;
                    float y1 = (acc[mt][nt][2 + p] - u1) * s1 + b1;
                    y1 = (y1 > 0.f) ? y1 : CSLOPE * y1;
                    mx1 = fmaxf(mx1, y1); sm1 += y1;
                }
            }
            #pragma unroll
            for (int off = 1; off <= 2; off <<= 1) {
                mx0 = fmaxf(mx0, __shfl_xor_sync(0xffffffffu, mx0, off));
                sm0 += __shfl_xor_sync(0xffffffffu, sm0, off);
                mx1 = fmaxf(mx1, __shfl_xor_sync(0xffffffffu, mx1, off));
                sm1 += __shfl_xor_sync(0xffffffffu, sm1, off);
            }
            if (qc == 0) {
                smax[rl2][wn] = mx0; ssum[rl2][wn] = sm0;
                smax[rl2 + 8][wn] = mx1; ssum[rl2 + 8][wn] = sm1;
            }
        }
        __syncthreads();
        if (tid < 128) {
            float mx = -INFINITY, sm = 0.f;
            #pragma unroll
            for (int w = 0; w < 4; w++) { mx = fmaxf(mx, smax[tid][w]); sm += ssum[tid][w]; }
            size_t o = (size_t)z * NPTS + m0 + tid;
            g_pmax[o * 8 + blockIdx.x] = mx;
            g_psum[o * 8 + blockIdx.x] = sm;
        }
    }
}

// ================= top-20 selection =================
__device__ __forceinline__ void select20(float d[32], int lane, int* myidx) {
    float lm = -INFINITY; int lj = 0;
    #pragma unroll
    for (int j = 0; j < 32; j++) if (d[j] > lm) { lm = d[j]; lj = j; }
    for (int k = 0; k < KNB; k++) {
        float bv = lm; int bidx = lj * 32 + lane;
        #pragma unroll
        for (int off = 16; off > 0; off >>= 1) {
            float ov = __shfl_xor_sync(0xffffffffu, bv, off);
            int   oi = __shfl_xor_sync(0xffffffffu, bidx, off);
            if (ov > bv || (ov == bv && oi < bidx)) { bv = ov; bidx = oi; }
        }
        if (lane == (bidx & 31)) {
            int jj = bidx >> 5;
            lm = -INFINITY; lj = 0;
            #pragma unroll
            for (int j = 0; j < 32; j++) {
                if (j == jj) d[j] = -INFINITY;
                if (d[j] > lm) { lm = d[j]; lj = j; }
            }
        }
        if (lane == 0) myidx[k] = bidx;
    }
}

__global__ void __launch_bounds__(256) topk_kernel() {
    const int tid = threadIdx.x, lane = tid & 31;
    const int gw = blockIdx.x * 8 + (tid >> 5);
    const int b = gw >> 10, n = gw & 1023;
    const float* Grow = g_gram + ((size_t)b * NPTS + n) * NPTS;
    const float* xxb = g_xx + b * NPTS;
    float d[32];
    #pragma unroll
    for (int j = 0; j < 32; j++) {
        int m = j * 32 + lane;
        d[j] = 2.f * Grow[m] - xxb[m];
    }
    select20(d, lane, g_idx + ((size_t)b * NPTS + n) * KNB);
}

// block-1 topk: C=3 distances inline, exact fp32
__global__ void __launch_bounds__(256) topk3_kernel(const float* __restrict__ x) {
    const int tid = threadIdx.x, lane = tid & 31;
    const int gw = blockIdx.x * 8 + (tid >> 5);
    const int b = gw >> 10, n = gw & 1023;
    const float* xb = x + (size_t)b * 3 * NPTS;
    float c0 = xb[n], c1 = xb[NPTS + n], c2 = xb[2 * NPTS + n];
    float d[32];
    #pragma unroll
    for (int j = 0; j < 32; j++) {
        int m = j * 32 + lane;
        float v0 = xb[m], v1 = xb[NPTS + m], v2 = xb[2 * NPTS + m];
        float dot = fmaf(v2, c2, fmaf(v1, c1, fmaf(v0, c0, 0.f)));
        float xxm = fmaf(v2, v2, fmaf(v1, v1, fmaf(v0, v0, 0.f)));
        d[j] = 2.f * dot - xxm;
    }
    select20(d, lane, g_idx + ((size_t)b * NPTS + n) * KNB);
}

// weight/input pre-split packing (runs on side stream, overlapped with topk3)
__global__ void __launch_bounds__(256) pack_kernel(
    const float* __restrict__ x,
    const float* __restrict__ w0, const float* __restrict__ w1,
    const float* __restrict__ w2, const float* __restrict__ w3,
    const float* __restrict__ we)
{
    const int gstride = gridDim.x * 256;
    int gid = blockIdx.x * 256 + threadIdx.x;

    for (int i = gid; i < BATCH * NPTS; i += gstride) {
        int bb = i >> 10, nn = i & 1023;
        const float* xr = x + (size_t)bb * 3 * NPTS;
        float v0 = xr[nn], v1 = xr[NPTS + nn], v2 = xr[2 * NPTS + nn];
        g_xH[(bb * 2 + 0) * NPTS + nn] = packh(v0, v1);
        g_xL[(bb * 2 + 0) * NPTS + nn] = packl(v0, v1);
        g_xH[(bb * 2 + 1) * NPTS + nn] = packh(v2, 0.f);
        g_xL[(bb * 2 + 1) * NPTS + nn] = packl(v2, 0.f);
    }
    for (int i = gid; i < WTOTU; i += gstride) {
        const float* w; int C, O, loc;
        if (i < WSEG1)      { w = w0; C = 3;   O = 64;  loc = i - WSEG0; }
        else if (i < WSEG2) { w = w1; C = 64;  O = 64;  loc = i - WSEG1; }
        else if (i < WSEG3) { w = w2; C = 64;  O = 128; loc = i - WSEG2; }
        else                { w = w3; C = 128; O = 256; loc = i - WSEG3; }
        int N2 = 2 * O, p = loc / N2, j = loc - p * N2;
        int k0 = 2 * p, k1 = 2 * p + 1;
        float v0, v1;
        if (j < O) {
            v0 = w[(size_t)j * 2 * C + k0];
            v1 = (k1 < C) ? w[(size_t)j * 2 * C + k1] : 0.f;
        } else {
            int o = j - O;
            v0 = w[(size_t)o * 2 * C + C + k0] - w[(size_t)o * 2 * C + k0];
            v1 = (k1 < C) ? (w[(size_t)o * 2 * C + C + k1] - w[(size_t)o * 2 * C + k1]) : 0.f;
        }
        g_WtH[i] = packh(v0, v1);
        g_WtL[i] = packl(v0, v1);
    }
    for (int i = gid; i < 256 * 1024; i += gstride) {
        int p = i >> 10, o = i & 1023;
        float v0 = we[(size_t)o * 512 + 2 * p];
        float v1 = we[(size_t)o * 512 + 2 * p + 1];
        g_weTH[i] = packh(v0, v1);
        g_weTL[i] = packl(v0, v1);
    }
}

// ================= conv epilogue =================
template<int O, bool WX>
__global__ void __launch_bounds__(O) cepi_kernel(const float* __restrict__ bnp, int cout_off) {
    const int b = blockIdx.y, n = blockIdx.x, o = threadIdx.x;
    const int lane = o & 31, wid = o >> 5;
    __shared__ int jid[KNB];
    if (o < KNB) jid[o] = g_idx[((size_t)b * NPTS + n) * KNB + o];
    __syncthreads();
    const int ld = 2 * O;
    const size_t rowbase = (size_t)b * NPTS;
    float mx = -INFINITY;
    #pragma unroll 4
    for (int k = 0; k < KNB; k++)
        mx = fmaxf(mx, g_Z[(rowbase + jid[k]) * ld + o]);
    mx += g_Z[(rowbase + n) * ld + O + o];
    float gg = bnp[o], bb = bnp[O + o], mm = bnp[2 * O + o], vv = bnp[3 * O + o];
    float scale = gg / sqrtf(vv + CEPS);
    float y = (mx - mm) * scale + bb;
    y = (y > 0.f) ? y : CSLOPE * y;

    int c = cout_off + o;
    size_t hidx = (((size_t)b * 256 + (c >> 1)) * NPTS + n) * 2 + (c & 1);
    __half hh = __float2half_rn(y);
    g_catH[hidx] = hh;
    g_catL[hidx] = __float2half_rn(y - __half2float(hh));

    if (WX) {
        float s = y * y;
        #pragma unroll
        for (int off = 16; off > 0; off >>= 1) s += __shfl_xor_sync(0xffffffffu, s, off);
        __shared__ float ws[O / 32];
        if (lane == 0) ws[wid] = s;
        __syncthreads();
        if (o == 0) {
            float t = 0.f;
            #pragma unroll
            for (int w = 0; w < O / 32; w++) t += ws[w];
            g_xx[b * NPTS + n] = t;
        }
    }
}

// ================= fused MLP head (coalesced, warp-per-output) =================
__global__ void __launch_bounds__(1024) head_kernel(
    const float* __restrict__ wf0, const float* __restrict__ bnf0,
    const float* __restrict__ wf1, const float* __restrict__ bnf1,
    const float* __restrict__ wfin, const float* __restrict__ bfin,
    float* __restrict__ out)
{
    const int b = blockIdx.x, tid = threadIdx.x;
    const int w = tid >> 5, lane = tid & 31;
    __shared__ float h0s[2048];
    __shared__ float h1s[512];
    __shared__ float h2s[256];

    {   // finish embed pools (one thread per o)
        int o = tid;
        size_t base = ((size_t)b * NPTS + o) * 8;
        float mx = -INFINITY, sm = 0.f;
        #pragma unroll
        for (int t = 0; t < 8; t++) { mx = fmaxf(mx, g_pmax[base + t]); sm += g_psum[base + t]; }
        h0s[o] = mx;
        h0s[1024 + o] = sm * (1.0f / 1024.0f);
    }
    __syncthreads();

    // h1 (512 outputs, 16 per warp), lane-strided coalesced weight reads
    for (int j = 0; j < 16; j++) {
        int o = w * 16 + j;
        const float* wr = wf0 + (size_t)o * 2048;
        float a = 0.f;
        #pragma unroll 4
        for (int c = lane * 4; c < 2048; c += 128) {
            float4 wv = *(const float4*)(wr + c);
            a = fmaf(wv.x, h0s[c], a);
            a = fmaf(wv.y, h0s[c + 1], a);
            a = fmaf(wv.z, h0s[c + 2], a);
            a = fmaf(wv.w, h0s[c + 3], a);
        }
        #pragma unroll
        for (int off = 16; off > 0; off >>= 1) a += __shfl_xor_sync(0xffffffffu, a, off);
        if (lane == 0) {
            float scale = bnf0[o] / sqrtf(bnf0[1536 + o] + CEPS);
            float y = (a - bnf0[1024 + o]) * scale + bnf0[512 + o];
            h1s[o] = (y > 0.f) ? y : CSLOPE * y;
        }
    }
    __syncthreads();

    // h2 (256 outputs, 8 per warp)
    for (int j = 0; j < 8; j++) {
        int o = w * 8 + j;
        const float* wr = wf1 + (size_t)o * 512;
        float a = 0.f;
        #pragma unroll
        for (int c = lane * 4; c < 512; c += 128) {
            float4 wv = *(const float4*)(wr + c);
            a = fmaf(wv.x, h1s[c], a);
            a = fmaf(wv.y, h1s[c + 1], a);
            a = fmaf(wv.z, h1s[c + 2], a);
            a = fmaf(wv.w, h1s[c + 3], a);
        }
        #pragma unroll
        for (int off = 16; off > 0; off >>= 1) a += __shfl_xor_sync(0xffffffffu, a, off);
        if (lane == 0) {
            float scale = bnf1[o] / sqrtf(bnf1[768 + o] + CEPS);
            float y = (a - bnf1[512 + o]) * scale + bnf1[256 + o];
            h2s[o] = (y > 0.f) ? y : CSLOPE * y;
        }
    }
    __syncthreads();

    // final (64 outputs, 2 per warp)
    for (int j = 0; j < 2; j++) {
        int o = w * 2 + j;
        const float* wr = wfin + (size_t)o * 256;
        float a = 0.f;
        #pragma unroll
        for (int c = lane * 4; c < 256; c += 128) {
            float4 wv = *(const float4*)(wr + c);
            a = fmaf(wv.x, h2s[c], a);
            a = fmaf(wv.y, h2s[c + 1], a);
            a = fmaf(wv.z, h2s[c + 2], a);
            a = fmaf(wv.w, h2s[c + 3], a);
        }
        #pragma unroll
        for (int off = 16; off > 0; off >>= 1) a += __shfl_xor_sync(0xffffffffu, a, off);
        if (lane == 0) out[b * 64 + o] = bfin[o] + a;
    }
}

// ================= launch =================
#define GSMEM 69632

extern "C" void kernel_launch(void* const* d_in, const int* in_sizes, int n_in,
                              void* d_out, int out_size) {
    const float* x    = (const float*)d_in[0];
    const float* w0   = (const float*)d_in[1];
    const float* w1   = (const float*)d_in[2];
    const float* w2   = (const float*)d_in[3];
    const float* w3   = (const float*)d_in[4];
    const float* bn0  = (const float*)d_in[5];
    const float* bn1  = (const float*)d_in[6];
    const float* bn2  = (const float*)d_in[7];
    const float* bn3  = (const float*)d_in[8];
    const float* we   = (const float*)d_in[9];
    const float* bne  = (const float*)d_in[10];
    const float* wf0  = (const float*)d_in[11];
    const float* bnf0 = (const float*)d_in[12];
    const float* wf1  = (const float*)d_in[13];
    const float* bnf1 = (const float*)d_in[14];
    const float* wfin = (const float*)d_in[15];
    const float* bfin = (const float*)d_in[16];

    static bool s_init = false;
    static cudaStream_t s1;
    static cudaEvent_t evS, evJ[4], evF[3];
    if (!s_init) {
        cudaStreamCreateWithFlags(&s1, cudaStreamNonBlocking);
        cudaEventCreateWithFlags(&evS, cudaEventDisableTiming);
        for (int i = 0; i < 4; i++) cudaEventCreateWithFlags(&evJ[i], cudaEventDisableTiming);
        for (int i = 0; i < 3; i++) cudaEventCreateWithFlags(&evF[i], cudaEventDisableTiming);
        cudaFuncSetAttribute(gemm16<false>, cudaFuncAttributeMaxDynamicSharedMemorySize, GSMEM);
        cudaFuncSetAttribute(gemm16<true>,  cudaFuncAttributeMaxDynamicSharedMemorySize, GSMEM);
        s_init = true;
    }

    float *Zp, *gramp;
    uint32_t *catHp, *catLp, *WtHp, *WtLp, *weTHp, *weTLp, *xHp, *xLp;
    cudaGetSymbolAddress((void**)&Zp, g_Z);
    cudaGetSymbolAddress((void**)&gramp, g_gram);
    cudaGetSymbolAddress((void**)&catHp, g_catH);
    cudaGetSymbolAddress((void**)&catLp, g_catL);
    cudaGetSymbolAddress((void**)&WtHp, g_WtH);
    cudaGetSymbolAddress((void**)&WtLp, g_WtL);
    cudaGetSymbolAddress((void**)&weTHp, g_weTH);
    cudaGetSymbolAddress((void**)&weTLp, g_weTL);
    cudaGetSymbolAddress((void**)&xHp, g_xH);
    cudaGetSymbolAddress((void**)&xLp, g_xL);

    dim3 gpn(NPTS, BATCH);
    const size_t sCat = (size_t)256 * NPTS;
    const size_t sG = (size_t)NPTS * NPTS;
    cudaStream_t s0 = 0;

    // fork: pack + Z1 on s1, topk3 on main
    cudaEventRecord(evS, s0);
    cudaStreamWaitEvent(s1, evS, 0);
    pack_kernel<<<1024, 256, 0, s1>>>(x, w0, w1, w2, w3, we);
    topk3_kernel<<<1024, 256>>>(x);
    gemm16<false><<<dim3(1, 8, BATCH), 256, GSMEM, s1>>>(
        xHp, xLp, WtHp + WSEG0, WtLp + WSEG0, Zp, nullptr,
        2, NPTS, 128, 128, (size_t)2 * NPTS, 0, (size_t)NPTS * 128);
    cudaEventRecord(evJ[0], s1);
    cudaStreamWaitEvent(s0, evJ[0], 0);
    cepi_kernel<64, true><<<gpn, 64>>>(bn0, 0);

    // block 2: Z2 on s1 || gram2+topk2 on main
    cudaEventRecord(evF[0], s0);
    cudaStreamWaitEvent(s1, evF[0], 0);
    gemm16<false><<<dim3(1, 8, BATCH), 256, GSMEM, s1>>>(
        catHp, catLp, WtHp + WSEG1, WtLp + WSEG1, Zp, nullptr,
        32, NPTS, 128, 128, sCat, 0, (size_t)NPTS * 128);
    cudaEventRecord(evJ[1], s1);
    gemm16<false><<<dim3(8, 8, BATCH), 256, GSMEM>>>(
        catHp, catLp, catHp, catLp, gramp, nullptr,
        32, NPTS, NPTS, NPTS, sCat, sCat, sG);
    topk_kernel<<<1024, 256>>>();
    cudaStreamWaitEvent(s0, evJ[1], 0);
    cepi_kernel<64, true><<<gpn, 64>>>(bn1, 64);

    // block 3
    cudaEventRecord(evF[1], s0);
    cudaStreamWaitEvent(s1, evF[1], 0);
    gemm16<false><<<dim3(2, 8, BATCH), 256, GSMEM, s1>>>(
        catHp + 32 * NPTS, catLp + 32 * NPTS, WtHp + WSEG2, WtLp + WSEG2, Zp, nullptr,
        32, NPTS, 256, 256, sCat, 0, (size_t)NPTS * 256);
    cudaEventRecord(evJ[2], s1);
    gemm16<false><<<dim3(8, 8, BATCH), 256, GSMEM>>>(
        catHp + 32 * NPTS, catLp + 32 * NPTS, catHp + 32 * NPTS, catLp + 32 * NPTS, gramp, nullptr,
        32, NPTS, NPTS, NPTS, sCat, sCat, sG);
    topk_kernel<<<1024, 256>>>();
    cudaStreamWaitEvent(s0, evJ[2], 0);
    cepi_kernel<128, true><<<gpn, 128>>>(bn2, 128);

    // block 4
    cudaEventRecord(evF[2], s0);
    cudaStreamWaitEvent(s1, evF[2], 0);
    gemm16<false><<<dim3(4, 8, BATCH), 256, GSMEM, s1>>>(
        catHp + 64 * NPTS, catLp + 64 * NPTS, WtHp + WSEG3, WtLp + WSEG3, Zp, nullptr,
        64, NPTS, 512, 512, sCat, 0, (size_t)NPTS * 512);
    cudaEventRecord(evJ[3], s1);
    gemm16<false><<<dim3(8, 8, BATCH), 256, GSMEM>>>(
        catHp + 64 * NPTS, catLp + 64 * NPTS, catHp + 64 * NPTS, catLp + 64 * NPTS, gramp, nullptr,
        64, NPTS, NPTS, NPTS, sCat, sCat, sG);
    topk_kernel<<<1024, 256>>>();
    cudaStreamWaitEvent(s0, evJ[3], 0);
    cepi_kernel<256, false><<<gpn, 256>>>(bn3, 256);

    // embedding GEMM with fused BN+lrelu+pool partials
    gemm16<true><<<dim3(8, 8, BATCH), 256, GSMEM>>>(
        weTHp, weTLp, catHp, catLp, nullptr, bne,
        256, NPTS, NPTS, 0, 0, sCat, 0);

    // fused MLP head
    head_kernel<<<BATCH, 1024>>>(wf0, bnf0, wf1, bnf1, wfin, bfin, (float*)d_out);
}

// round 12
// speedup vs baseline: 2.9023x; 1.0881x over previous
#include <cuda_runtime.h>
#include <cuda_fp16.h>
#include <math.h>
#include <stdint.h>

#define NPTS 1024
#define KNB 20
#define BATCH 8
#define CEPS 1e-5f
#define CSLOPE 0.2f

// ---------------- scratch (no allocations allowed) ----------------
// cat stored pre-split as half2 pair words: word index (b*256 + c/2)*NPTS + n
__device__ uint32_t g_catH[(size_t)BATCH * 256 * NPTS];
__device__ uint32_t g_catL[(size_t)BATCH * 256 * NPTS];
__device__ float    g_gram[(size_t)BATCH * NPTS * NPTS];
__device__ float    g_xx[BATCH * NPTS];
__device__ int      g_idx[(size_t)BATCH * NPTS * KNB];
__device__ float    g_Z[(size_t)BATCH * NPTS * 512];
__device__ uint32_t g_WtH[45312], g_WtL[45312];
__device__ uint32_t g_weTH[256 * 1024], g_weTL[256 * 1024];
__device__ uint32_t g_xH[BATCH * 2 * NPTS], g_xL[BATCH * 2 * NPTS];
__device__ float    g_pmax[BATCH * NPTS * 8];
__device__ float    g_psum[BATCH * NPTS * 8];

#define WSEG0 0
#define WSEG1 256
#define WSEG2 4352
#define WSEG3 12544
#define WTOTU 45312

// ================= helpers =================
__device__ __forceinline__ uint32_t packh(float a, float b) {
    __half2 h = __halves2half2(__float2half_rn(a), __float2half_rn(b));
    return *(uint32_t*)&h;
}
__device__ __forceinline__ uint32_t packl(float a, float b) {
    float ra = a - __half2float(__float2half_rn(a));
    float rb = b - __half2float(__float2half_rn(b));
    __half2 h = __halves2half2(__float2half_rn(ra), __float2half_rn(rb));
    return *(uint32_t*)&h;
}
__device__ __forceinline__ void mma16(float* c, const uint32_t* a, const uint32_t* b) {
    asm volatile(
        "mma.sync.aligned.m16n8k16.row.col.f32.f16.f16.f32 "
        "{%0,%1,%2,%3}, {%4,%5,%6,%7}, {%8,%9}, {%0,%1,%2,%3};\n"
        : "+f"(c[0]), "+f"(c[1]), "+f"(c[2]), "+f"(c[3])
        : "r"(a[0]), "r"(a[1]), "r"(a[2]), "r"(a[3]), "r"(b[0]), "r"(b[1]));
}
__device__ __forceinline__ void cpa16(uint32_t s, const void* g, int ok) {
    asm volatile("cp.async.cg.shared.global [%0], [%1], 16, %2;"
                 :: "r"(s), "l"(g), "r"(ok ? 16 : 0));
}
__device__ __forceinline__ void cpa_commit() { asm volatile("cp.async.commit_group;"); }
template<int N> __device__ __forceinline__ void cpa_wait() {
    asm volatile("cp.async.wait_group %0;" :: "n"(N));
}

// ================= fp16-split GEMM, cp.async double-buffered =================
template<bool POOL>
__global__ void __launch_bounds__(256) gemm16(
    const uint32_t* __restrict__ Ahg, const uint32_t* __restrict__ Alg,
    const uint32_t* __restrict__ Bhg, const uint32_t* __restrict__ Blg,
    float* __restrict__ Cc, const float* __restrict__ bne,
    int KP, int lda, int ldb, int ldc, size_t sAz, size_t sBz, size_t sCz)
{
    extern __shared__ __align__(16) uint32_t smbuf[];
    const int z = blockIdx.z;
    const int m0 = blockIdx.y * 128, n0 = blockIdx.x * 128;
    const uint32_t* Abh = Ahg + z * sAz + m0;
    const uint32_t* Abl = Alg + z * sAz + m0;
    const uint32_t* Bbh = Bhg + z * sBz + n0;
    const uint32_t* Bbl = Blg + z * sBz + n0;

    const int tid = threadIdx.x, lane = tid & 31, wrp = tid >> 5;
    const int wm = wrp >> 2, wn = wrp & 3;
    const int qr = lane >> 2, qc = lane & 3;

    float acc[4][4][4];
    #pragma unroll
    for (int i = 0; i < 4; i++)
        #pragma unroll
        for (int j = 0; j < 4; j++)
            #pragma unroll
            for (int q = 0; q < 4; q++) acc[i][j][q] = 0.f;

    const int r0 = tid >> 5, c0 = (tid & 31) * 4;
    const int r1 = r0 + 8;
    const uint32_t smbase = (uint32_t)__cvta_generic_to_shared(smbuf);
    const int KT = (KP + 15) / 16;

    auto issue = [&](int kt, int buf) {
        const int rl = KP - kt * 16;
        const size_t ko = (size_t)kt * 16;
        const uint32_t bb = smbase + (uint32_t)buf * (8704u * 4u);
        const uint32_t* pAh = Abh + ko * lda;
        const uint32_t* pAl = Abl + ko * lda;
        const uint32_t* pBh = Bbh + ko * ldb;
        const uint32_t* pBl = Bbl + ko * ldb;
        uint32_t d0 = bb + (uint32_t)(r0 * 136 + c0) * 4u;
        uint32_t d1 = bb + (uint32_t)(r1 * 136 + c0) * 4u;
        cpa16(d0,             pAh + (size_t)r0 * lda + c0, r0 < rl);
        cpa16(d1,             pAh + (size_t)r1 * lda + c0, r1 < rl);
        cpa16(d0 + 2176u * 4, pAl + (size_t)r0 * lda + c0, r0 < rl);
        cpa16(d1 + 2176u * 4, pAl + (size_t)r1 * lda + c0, r1 < rl);
        cpa16(d0 + 4352u * 4, pBh + (size_t)r0 * ldb + c0, r0 < rl);
        cpa16(d1 + 4352u * 4, pBh + (size_t)r1 * ldb + c0, r1 < rl);
        cpa16(d0 + 6528u * 4, pBl + (size_t)r0 * ldb + c0, r0 < rl);
        cpa16(d1 + 6528u * 4, pBl + (size_t)r1 * ldb + c0, r1 < rl);
        cpa_commit();
    };

    issue(0, 0);
    for (int kt = 0; kt < KT; kt++) {
        const int cur = kt & 1;
        if (kt + 1 < KT) { issue(kt + 1, cur ^ 1); cpa_wait<1>(); }
        else             { cpa_wait<0>(); }
        __syncthreads();
        const uint32_t* Ah = smbuf + cur * 8704;
        const uint32_t* Al = Ah + 2176;
        const uint32_t* Bh = Ah + 4352;
        const uint32_t* Bl = Ah + 6528;
        #pragma unroll
        for (int kk = 0; kk < 2; kk++) {
            const int kb = kk * 8;
            uint32_t ah[4][4], al[4][4], bh[4][2], bl[4][2];
            #pragma unroll
            for (int mt = 0; mt < 4; mt++) {
                int R = wm * 64 + mt * 16;
                ah[mt][0] = Ah[(kb + qc) * 136 + R + qr];
                ah[mt][1] = Ah[(kb + qc) * 136 + R + qr + 8];
                ah[mt][2] = Ah[(kb + qc + 4) * 136 + R + qr];
                ah[mt][3] = Ah[(kb + qc + 4) * 136 + R + qr + 8];
                al[mt][0] = Al[(kb + qc) * 136 + R + qr];
                al[mt][1] = Al[(kb + qc) * 136 + R + qr + 8];
                al[mt][2] = Al[(kb + qc + 4) * 136 + R + qr];
                al[mt][3] = Al[(kb + qc + 4) * 136 + R + qr + 8];
            }
            #pragma unroll
            for (int nt = 0; nt < 4; nt++) {
                int C0 = wn * 32 + nt * 8;
                bh[nt][0] = Bh[(kb + qc) * 136 + C0 + qr];
                bh[nt][1] = Bh[(kb + qc + 4) * 136 + C0 + qr];
                bl[nt][0] = Bl[(kb + qc) * 136 + C0 + qr];
                bl[nt][1] = Bl[(kb + qc + 4) * 136 + C0 + qr];
            }
            #pragma unroll
            for (int mt = 0; mt < 4; mt++)
                #pragma unroll
                for (int nt = 0; nt < 4; nt++) {
                    mma16(acc[mt][nt], ah[mt], bh[nt]);
                    mma16(acc[mt][nt], al[mt], bh[nt]);
                    mma16(acc[mt][nt], ah[mt], bl[nt]);
                }
        }
        __syncthreads();
    }

    if (!POOL) {
        float* Cb = Cc + z * sCz;
        #pragma unroll
        for (int mt = 0; mt < 4; mt++)
            #pragma unroll
            for (int nt = 0; nt < 4; nt++) {
                int r = m0 + wm * 64 + mt * 16 + qr;
                int cc = n0 + wn * 32 + nt * 8 + 2 * qc;
                *(float2*)(Cb + (size_t)r * ldc + cc)       = make_float2(acc[mt][nt][0], acc[mt][nt][1]);
                *(float2*)(Cb + (size_t)(r + 8) * ldc + cc) = make_float2(acc[mt][nt][2], acc[mt][nt][3]);
            }
    } else {
        __shared__ float smax[128][5], ssum[128][5];
        #pragma unroll
        for (int mt = 0; mt < 4; mt++) {
            int rl2 = wm * 64 + mt * 16 + qr;
            int o0 = m0 + rl2, o1 = o0 + 8;
            float s0 = bne[o0] / sqrtf(bne[3072 + o0] + CEPS);
            float b0 = bne[1024 + o0], u0 = bne[2048 + o0];
            float s1 = bne[o1] / sqrtf(bne[3072 + o1] + CEPS);
            float b1 = bne[1024 + o1], u1 = bne[2048 + o1];
            float mx0 = -INFINITY, sm0 = 0.f, mx1 = -INFINITY, sm1 = 0.f;
            #pragma unroll
            for (int nt = 0; nt < 4; nt++) {
                #pragma unroll
                for (int p = 0; p < 2; p++) {
                    float y0 = (acc[mt][nt][p] - u0) * s0 + b0;
                    y0 = (y0 > 0.f) ? y0 : CSLOPE * y0;
                    mx0 = fmaxf(mx0, y0); sm0 += y0;
                    float y1 = (acc[mt][nt][2 + p] - u1) * s1 + b1;
                    y1 = (y1 > 0.f) ? y1 : CSLOPE * y1;
                    mx1 = fmaxf(mx1, y1); sm1 += y1;
                }
            }
            #pragma unroll
            for (int off = 1; off <= 2; off <<= 1) {
                mx0 = fmaxf(mx0, __shfl_xor_sync(0xffffffffu, mx0, off));
                sm0 += __shfl_xor_sync(0xffffffffu, sm0, off);
                mx1 = fmaxf(mx1, __shfl_xor_sync(0xffffffffu, mx1, off));
                sm1 += __shfl_xor_sync(0xffffffffu, sm1, off);
            }
            if (qc == 0) {
                smax[rl2][wn] = mx0; ssum[rl2][wn] = sm0;
                smax[rl2 + 8][wn] = mx1; ssum[rl2 + 8][wn] = sm1;
            }
        }
        __syncthreads();
        if (tid < 128) {
            float mx = -INFINITY, sm = 0.f;
            #pragma unroll
            for (int w = 0; w < 4; w++) { mx = fmaxf(mx, smax[tid][w]); sm += ssum[tid][w]; }
            size_t o = (size_t)z * NPTS + m0 + tid;
            g_pmax[o * 8 + blockIdx.x] = mx;
            g_psum[o * 8 + blockIdx.x] = sm;
        }
    }
}

// ================= block-1 topk: selection only (overlaps pack+Z1) =================
__global__ void __launch_bounds__(256) topk3_kernel(const float* __restrict__ x) {
    const int tid = threadIdx.x, lane = tid & 31;
    const int gw = blockIdx.x * 8 + (tid >> 5);
    const int b = gw >> 10, n = gw & 1023;
    const float* xb = x + (size_t)b * 3 * NPTS;
    float c0 = xb[n], c1 = xb[NPTS + n], c2 = xb[2 * NPTS + n];
    float d[32];
    #pragma unroll
    for (int j = 0; j < 32; j++) {
        int m = j * 32 + lane;
        float v0 = xb[m], v1 = xb[NPTS + m], v2 = xb[2 * NPTS + m];
        float dot = fmaf(v2, c2, fmaf(v1, c1, fmaf(v0, c0, 0.f)));
        float xxm = fmaf(v2, v2, fmaf(v1, v1, fmaf(v0, v0, 0.f)));
        d[j] = 2.f * dot - xxm;
    }
    int* myidx = g_idx + ((size_t)b * NPTS + n) * KNB;
    float lm = -INFINITY; int lj = 0;
    #pragma unroll
    for (int j = 0; j < 32; j++) if (d[j] > lm) { lm = d[j]; lj = j; }
    for (int k = 0; k < KNB; k++) {
        float bv = lm; int bidx = lj * 32 + lane;
        #pragma unroll
        for (int off = 16; off > 0; off >>= 1) {
            float ov = __shfl_xor_sync(0xffffffffu, bv, off);
            int   oi = __shfl_xor_sync(0xffffffffu, bidx, off);
            if (ov > bv || (ov == bv && oi < bidx)) { bv = ov; bidx = oi; }
        }
        if (lane == (bidx & 31)) {
            int jj = bidx >> 5;
            lm = -INFINITY; lj = 0;
            #pragma unroll
            for (int j = 0; j < 32; j++) {
                if (j == jj) d[j] = -INFINITY;
                if (d[j] > lm) { lm = d[j]; lj = j; }
            }
        }
        if (lane == 0) myidx[k] = bidx;
    }
}

// ================= fused topk + conv-epilogue =================
// 8 points per 256-thread block, warp-per-point.
// SEL: select top-20 from gram/xx; else read g_idx. Then gather Z rows, max,
// +center, BN+lrelu, xx (if WX), coalesced pair-word cat writes.
template<int O, bool WX, bool SEL>
__global__ void __launch_bounds__(256) tkcepi_kernel(const float* __restrict__ bnp, int cout_off) {
    constexpr int NCH = O / 32;
    const int tid = threadIdx.x, lane = tid & 31, wrp = tid >> 5;
    const int b = blockIdx.y;
    const int n = blockIdx.x * 8 + wrp;
    __shared__ float ys[8][O + 2];

    int mysel = 0;
    if (SEL) {
        const float* Grow = g_gram + ((size_t)b * NPTS + n) * NPTS;
        const float* xxb = g_xx + b * NPTS;
        float d[32];
        #pragma unroll
        for (int j = 0; j < 32; j++) {
            int m = j * 32 + lane;
            d[j] = 2.f * Grow[m] - xxb[m];
        }
        float lm = -INFINITY; int lj = 0;
        #pragma unroll
        for (int j = 0; j < 32; j++) if (d[j] > lm) { lm = d[j]; lj = j; }
        for (int k = 0; k < KNB; k++) {
            float bv = lm; int bidx = lj * 32 + lane;
            #pragma unroll
            for (int off = 16; off > 0; off >>= 1) {
                float ov = __shfl_xor_sync(0xffffffffu, bv, off);
                int   oi = __shfl_xor_sync(0xffffffffu, bidx, off);
                if (ov > bv || (ov == bv && oi < bidx)) { bv = ov; bidx = oi; }
            }
            if (lane == (bidx & 31)) {
                int jj = bidx >> 5;
                lm = -INFINITY; lj = 0;
                #pragma unroll
                for (int j = 0; j < 32; j++) {
                    if (j == jj) d[j] = -INFINITY;
                    if (d[j] > lm) { lm = d[j]; lj = j; }
                }
            }
            if (lane == k) mysel = bidx;
        }
    } else {
        if (lane < KNB) mysel = g_idx[((size_t)b * NPTS + n) * KNB + lane];
    }

    // gather 20 Z rows + max
    const int ld = 2 * O;
    const size_t rowbase = (size_t)b * NPTS;
    float mx[NCH];
    #pragma unroll
    for (int ch = 0; ch < NCH; ch++) mx[ch] = -INFINITY;
    for (int k = 0; k < KNB; k++) {
        int jk = __shfl_sync(0xffffffffu, mysel, k);
        const float* Zr = g_Z + (rowbase + jk) * ld;
        #pragma unroll
        for (int ch = 0; ch < NCH; ch++)
            mx[ch] = fmaxf(mx[ch], Zr[ch * 32 + lane]);
    }
    const float* Zc = g_Z + (rowbase + n) * ld + O;
    float xs = 0.f;
    #pragma unroll
    for (int ch = 0; ch < NCH; ch++) {
        int o = ch * 32 + lane;
        float v = mx[ch] + Zc[o];
        float scale = bnp[o] / sqrtf(bnp[3 * O + o] + CEPS);
        float y = (v - bnp[2 * O + o]) * scale + bnp[O + o];
        y = (y > 0.f) ? y : CSLOPE * y;
        ys[wrp][o] = y;
        if (WX) xs = fmaf(y, y, xs);
    }
    if (WX) {
        #pragma unroll
        for (int off = 16; off > 0; off >>= 1) xs += __shfl_xor_sync(0xffffffffu, xs, off);
        if (lane == 0) g_xx[b * NPTS + n] = xs;
    }
    __syncthreads();

    // coalesced pair-word writes: word (b*256 + cp)*NPTS + n, n fastest
    const int cp0 = cout_off >> 1;
    #pragma unroll
    for (int i = tid; i < 4 * O; i += 256) {
        int nl = i & 7, cp = i >> 3;
        float y0 = ys[nl][2 * cp], y1 = ys[nl][2 * cp + 1];
        size_t w = ((size_t)b * 256 + cp0 + cp) * NPTS + blockIdx.x * 8 + nl;
        g_catH[w] = packh(y0, y1);
        g_catL[w] = packl(y0, y1);
    }
}

// ================= pack: x/Wt strided + we smem-tile transpose =================
__global__ void __launch_bounds__(256) pack_kernel(
    const float* __restrict__ x,
    const float* __restrict__ w0, const float* __restrict__ w1,
    const float* __restrict__ w2, const float* __restrict__ w3,
    const float* __restrict__ we)
{
    const int tid = threadIdx.x;

    // we transpose: block handles 32 o x 64 c tile (32 pairs)
    {
        __shared__ float s[32][65];
        const int bo = blockIdx.x & 31, bp = blockIdx.x >> 5;
        const int o0 = bo * 32, c0 = bp * 64;
        #pragma unroll
        for (int i = tid; i < 32 * 64; i += 256) {
            int o = i >> 6, c = i & 63;
            s[o][c] = we[(size_t)(o0 + o) * 512 + c0 + c];
        }
        __syncthreads();
        #pragma unroll
        for (int i = tid; i < 32 * 32; i += 256) {
            int p = i >> 5, o = i & 31;
            float v0 = s[o][2 * p], v1 = s[o][2 * p + 1];
            int w = ((c0 >> 1) + p) * 1024 + o0 + o;
            g_weTH[w] = packh(v0, v1);
            g_weTL[w] = packl(v0, v1);
        }
    }

    const int gstride = gridDim.x * 256;
    int gid = blockIdx.x * 256 + tid;

    for (int i = gid; i < BATCH * NPTS; i += gstride) {
        int bb = i >> 10, nn = i & 1023;
        const float* xr = x + (size_t)bb * 3 * NPTS;
        float v0 = xr[nn], v1 = xr[NPTS + nn], v2 = xr[2 * NPTS + nn];
        g_xH[(bb * 2 + 0) * NPTS + nn] = packh(v0, v1);
        g_xL[(bb * 2 + 0) * NPTS + nn] = packl(v0, v1);
        g_xH[(bb * 2 + 1) * NPTS + nn] = packh(v2, 0.f);
        g_xL[(bb * 2 + 1) * NPTS + nn] = packl(v2, 0.f);
    }
    for (int i = gid; i < WTOTU; i += gstride) {
        const float* w; int C, O, loc;
        if (i < WSEG1)      { w = w0; C = 3;   O = 64;  loc = i - WSEG0; }
        else if (i < WSEG2) { w = w1; C = 64;  O = 64;  loc = i - WSEG1; }
        else if (i < WSEG3) { w = w2; C = 64;  O = 128; loc = i - WSEG2; }
        else                { w = w3; C = 128; O = 256; loc = i - WSEG3; }
        int N2 = 2 * O, p = loc / N2, j = loc - p * N2;
        int k0 = 2 * p, k1 = 2 * p + 1;
        float v0, v1;
        if (j < O) {
            v0 = w[(size_t)j * 2 * C + k0];
            v1 = (k1 < C) ? w[(size_t)j * 2 * C + k1] : 0.f;
        } else {
            int o = j - O;
            v0 = w[(size_t)o * 2 * C + C + k0] - w[(size_t)o * 2 * C + k0];
            v1 = (k1 < C) ? (w[(size_t)o * 2 * C + C + k1] - w[(size_t)o * 2 * C + k1]) : 0.f;
        }
        g_WtH[i] = packh(v0, v1);
        g_WtL[i] = packl(v0, v1);
    }
}

// ================= fused MLP head (coalesced, warp-per-output) =================
__global__ void __launch_bounds__(1024) head_kernel(
    const float* __restrict__ wf0, const float* __restrict__ bnf0,
    const float* __restrict__ wf1, const float* __restrict__ bnf1,
    const float* __restrict__ wfin, const float* __restrict__ bfin,
    float* __restrict__ out)
{
    const int b = blockIdx.x, tid = threadIdx.x;
    const int w = tid >> 5, lane = tid & 31;
    __shared__ float h0s[2048];
    __shared__ float h1s[512];
    __shared__ float h2s[256];

    {
        int o = tid;
        size_t base = ((size_t)b * NPTS + o) * 8;
        float mx = -INFINITY, sm = 0.f;
        #pragma unroll
        for (int t = 0; t < 8; t++) { mx = fmaxf(mx, g_pmax[base + t]); sm += g_psum[base + t]; }
        h0s[o] = mx;
        h0s[1024 + o] = sm * (1.0f / 1024.0f);
    }
    __syncthreads();

    for (int j = 0; j < 16; j++) {
        int o = w * 16 + j;
        const float* wr = wf0 + (size_t)o * 2048;
        float a = 0.f;
        #pragma unroll 4
        for (int c = lane * 4; c < 2048; c += 128) {
            float4 wv = *(const float4*)(wr + c);
            a = fmaf(wv.x, h0s[c], a);
            a = fmaf(wv.y, h0s[c + 1], a);
            a = fmaf(wv.z, h0s[c + 2], a);
            a = fmaf(wv.w, h0s[c + 3], a);
        }
        #pragma unroll
        for (int off = 16; off > 0; off >>= 1) a += __shfl_xor_sync(0xffffffffu, a, off);
        if (lane == 0) {
            float scale = bnf0[o] / sqrtf(bnf0[1536 + o] + CEPS);
            float y = (a - bnf0[1024 + o]) * scale + bnf0[512 + o];
            h1s[o] = (y > 0.f) ? y : CSLOPE * y;
        }
    }
    __syncthreads();

    for (int j = 0; j < 8; j++) {
        int o = w * 8 + j;
        const float* wr = wf1 + (size_t)o * 512;
        float a = 0.f;
        #pragma unroll
        for (int c = lane * 4; c < 512; c += 128) {
            float4 wv = *(const float4*)(wr + c);
            a = fmaf(wv.x, h1s[c], a);
            a = fmaf(wv.y, h1s[c + 1], a);
            a = fmaf(wv.z, h1s[c + 2], a);
            a = fmaf(wv.w, h1s[c + 3], a);
        }
        #pragma unroll
        for (int off = 16; off > 0; off >>= 1) a += __shfl_xor_sync(0xffffffffu, a, off);
        if (lane == 0) {
            float scale = bnf1[o] / sqrtf(bnf1[768 + o] + CEPS);
            float y = (a - bnf1[512 + o]) * scale + bnf1[256 + o];
            h2s[o] = (y > 0.f) ? y : CSLOPE * y;
        }
    }
    __syncthreads();

    for (int j = 0; j < 2; j++) {
        int o = w * 2 + j;
        const float* wr = wfin + (size_t)o * 256;
        float a = 0.f;
        #pragma unroll
        for (int c = lane * 4; c < 256; c += 128) {
            float4 wv = *(const float4*)(wr + c);
            a = fmaf(wv.x, h2s[c], a);
            a = fmaf(wv.y, h2s[c + 1], a);
            a = fmaf(wv.z, h2s[c + 2], a);
            a = fmaf(wv.w, h2s[c + 3], a);
        }
        #pragma unroll
        for (int off = 16; off > 0; off >>= 1) a += __shfl_xor_sync(0xffffffffu, a, off);
        if (lane == 0) out[b * 64 + o] = bfin[o] + a;
    }
}

// ================= launch =================
#define GSMEM 69632

extern "C" void kernel_launch(void* const* d_in, const int* in_sizes, int n_in,
                              void* d_out, int out_size) {
    const float* x    = (const float*)d_in[0];
    const float* w0   = (const float*)d_in[1];
    const float* w1   = (const float*)d_in[2];
    const float* w2   = (const float*)d_in[3];
    const float* w3   = (const float*)d_in[4];
    const float* bn0  = (const float*)d_in[5];
    const float* bn1  = (const float*)d_in[6];
    const float* bn2  = (const float*)d_in[7];
    const float* bn3  = (const float*)d_in[8];
    const float* we   = (const float*)d_in[9];
    const float* bne  = (const float*)d_in[10];
    const float* wf0  = (const float*)d_in[11];
    const float* bnf0 = (const float*)d_in[12];
    const float* wf1  = (const float*)d_in[13];
    const float* bnf1 = (const float*)d_in[14];
    const float* wfin = (const float*)d_in[15];
    const float* bfin = (const float*)d_in[16];

    static bool s_init = false;
    static cudaStream_t s1;
    static cudaEvent_t evS, evJ[4], evF[3];
    if (!s_init) {
        cudaStreamCreateWithFlags(&s1, cudaStreamNonBlocking);
        cudaEventCreateWithFlags(&evS, cudaEventDisableTiming);
        for (int i = 0; i < 4; i++) cudaEventCreateWithFlags(&evJ[i], cudaEventDisableTiming);
        for (int i = 0; i < 3; i++) cudaEventCreateWithFlags(&evF[i], cudaEventDisableTiming);
        cudaFuncSetAttribute(gemm16<false>, cudaFuncAttributeMaxDynamicSharedMemorySize, GSMEM);
        cudaFuncSetAttribute(gemm16<true>,  cudaFuncAttributeMaxDynamicSharedMemorySize, GSMEM);
        s_init = true;
    }

    float *Zp, *gramp;
    uint32_t *catHp, *catLp, *WtHp, *WtLp, *weTHp, *weTLp, *xHp, *xLp;
    cudaGetSymbolAddress((void**)&Zp, g_Z);
    cudaGetSymbolAddress((void**)&gramp, g_gram);
    cudaGetSymbolAddress((void**)&catHp, g_catH);
    cudaGetSymbolAddress((void**)&catLp, g_catL);
    cudaGetSymbolAddress((void**)&WtHp, g_WtH);
    cudaGetSymbolAddress((void**)&WtLp, g_WtL);
    cudaGetSymbolAddress((void**)&weTHp, g_weTH);
    cudaGetSymbolAddress((void**)&weTLp, g_weTL);
    cudaGetSymbolAddress((void**)&xHp, g_xH);
    cudaGetSymbolAddress((void**)&xLp, g_xL);

    dim3 gtk(128, BATCH);
    const size_t sCat = (size_t)256 * NPTS;
    const size_t sG = (size_t)NPTS * NPTS;
    cudaStream_t s0 = 0;

    // fork: pack + Z1 on s1, topk3 on main
    cudaEventRecord(evS, s0);
    cudaStreamWaitEvent(s1, evS, 0);
    pack_kernel<<<256, 256, 0, s1>>>(x, w0, w1, w2, w3, we);
    topk3_kernel<<<1024, 256>>>(x);
    gemm16<false><<<dim3(1, 8, BATCH), 256, GSMEM, s1>>>(
        xHp, xLp, WtHp + WSEG0, WtLp + WSEG0, Zp, nullptr,
        2, NPTS, 128, 128, (size_t)2 * NPTS, 0, (size_t)NPTS * 128);
    cudaEventRecord(evJ[0], s1);
    cudaStreamWaitEvent(s0, evJ[0], 0);
    tkcepi_kernel<64, true, false><<<gtk, 256>>>(bn0, 0);

    // block 2
    cudaEventRecord(evF[0], s0);
    cudaStreamWaitEvent(s1, evF[0], 0);
    gemm16<false><<<dim3(1, 8, BATCH), 256, GSMEM, s1>>>(
        catHp, catLp, WtHp + WSEG1, WtLp + WSEG1, Zp, nullptr,
        32, NPTS, 128, 128, sCat, 0, (size_t)NPTS * 128);
    cudaEventRecord(evJ[1], s1);
    gemm16<false><<<dim3(8, 8, BATCH), 256, GSMEM>>>(
        catHp, catLp, catHp, catLp, gramp, nullptr,
        32, NPTS, NPTS, NPTS, sCat, sCat, sG);
    cudaStreamWaitEvent(s0, evJ[1], 0);
    tkcepi_kernel<64, true, true><<<gtk, 256>>>(bn1, 64);

    // block 3
    cudaEventRecord(evF[1], s0);
    cudaStreamWaitEvent(s1, evF[1], 0);
    gemm16<false><<<dim3(2, 8, BATCH), 256, GSMEM, s1>>>(
        catHp + 32 * NPTS, catLp + 32 * NPTS, WtHp + WSEG2, WtLp + WSEG2, Zp, nullptr,
        32, NPTS, 256, 256, sCat, 0, (size_t)NPTS * 256);
    cudaEventRecord(evJ[2], s1);
    gemm16<false><<<dim3(8, 8, BATCH), 256, GSMEM>>>(
        catHp + 32 * NPTS, catLp + 32 * NPTS, catHp + 32 * NPTS, catLp + 32 * NPTS, gramp, nullptr,
        32, NPTS, NPTS, NPTS, sCat, sCat, sG);
    cudaStreamWaitEvent(s0, evJ[2], 0);
    tkcepi_kernel<128, true, true><<<gtk, 256>>>(bn2, 128);

    // block 4
    cudaEventRecord(evF[2], s0);
    cudaStreamWaitEvent(s1, evF[2], 0);
    gemm16<false><<<dim3(4, 8, BATCH), 256, GSMEM, s1>>>(
        catHp + 64 * NPTS, catLp + 64 * NPTS, WtHp + WSEG3, WtLp + WSEG3, Zp, nullptr,
        64, NPTS, 512, 512, sCat, 0, (size_t)NPTS * 512);
    cudaEventRecord(evJ[3], s1);
    gemm16<false><<<dim3(8, 8, BATCH), 256, GSMEM>>>(
        catHp + 64 * NPTS, catLp + 64 * NPTS, catHp + 64 * NPTS, catLp + 64 * NPTS, gramp, nullptr,
        64, NPTS, NPTS, NPTS, sCat, sCat, sG);
    cudaStreamWaitEvent(s0, evJ[3], 0);
    tkcepi_kernel<256, false, true><<<gtk, 256>>>(bn3, 256);

    // embedding GEMM with fused BN+lrelu+pool partials
    gemm16<true><<<dim3(8, 8, BATCH), 256, GSMEM>>>(
        weTHp, weTLp, catHp, catLp, nullptr, bne,
        256, NPTS, NPTS, 0, 0, sCat, 0);

    // fused MLP head
    head_kernel<<<BATCH, 1024>>>(wf0, bnf0, wf1, bnf1, wfin, bfin, (float*)d_out);
}

// round 13
// speedup vs baseline: 2.9394x; 1.0128x over previous
#include <cuda_runtime.h>
#include <cuda_fp16.h>
#include <math.h>
#include <stdint.h>

#define NPTS 1024
#define KNB 20
#define BATCH 8
#define CEPS 1e-5f
#define CSLOPE 0.2f

// ---------------- scratch (no allocations allowed) ----------------
__device__ uint32_t g_catH[(size_t)BATCH * 256 * NPTS];
__device__ uint32_t g_catL[(size_t)BATCH * 256 * NPTS];
__device__ float    g_gram[(size_t)BATCH * NPTS * NPTS];
__device__ float    g_E[(size_t)BATCH * 1024 * NPTS];    // embed partial (first K half)
__device__ float    g_xx[BATCH * NPTS];
__device__ int      g_idx[(size_t)BATCH * NPTS * KNB];
__device__ float    g_Z[(size_t)BATCH * NPTS * 512];
__device__ uint32_t g_WtH[45312], g_WtL[45312];
__device__ uint32_t g_weTH[256 * 1024], g_weTL[256 * 1024];
__device__ uint32_t g_xH[BATCH * 2 * NPTS], g_xL[BATCH * 2 * NPTS];
__device__ float    g_pmax[BATCH * NPTS * 8];
__device__ float    g_psum[BATCH * NPTS * 8];

#define WSEG0 0
#define WSEG1 256
#define WSEG2 4352
#define WSEG3 12544
#define WTOTU 45312

// ================= helpers =================
__device__ __forceinline__ uint32_t packh(float a, float b) {
    __half2 h = __halves2half2(__float2half_rn(a), __float2half_rn(b));
    return *(uint32_t*)&h;
}
__device__ __forceinline__ uint32_t packl(float a, float b) {
    float ra = a - __half2float(__float2half_rn(a));
    float rb = b - __half2float(__float2half_rn(b));
    __half2 h = __halves2half2(__float2half_rn(ra), __float2half_rn(rb));
    return *(uint32_t*)&h;
}
__device__ __forceinline__ void mma16(float* c, const uint32_t* a, const uint32_t* b) {
    asm volatile(
        "mma.sync.aligned.m16n8k16.row.col.f32.f16.f16.f32 "
        "{%0,%1,%2,%3}, {%4,%5,%6,%7}, {%8,%9}, {%0,%1,%2,%3};\n"
        : "+f"(c[0]), "+f"(c[1]), "+f"(c[2]), "+f"(c[3])
        : "r"(a[0]), "r"(a[1]), "r"(a[2]), "r"(a[3]), "r"(b[0]), "r"(b[1]));
}
__device__ __forceinline__ void cpa16(uint32_t s, const void* g, int ok) {
    asm volatile("cp.async.cg.shared.global [%0], [%1], 16, %2;"
                 :: "r"(s), "l"(g), "r"(ok ? 16 : 0));
}
__device__ __forceinline__ void cpa_commit() { asm volatile("cp.async.commit_group;"); }
template<int N> __device__ __forceinline__ void cpa_wait() {
    asm volatile("cp.async.wait_group %0;" :: "n"(N));
}

// ================= shared GEMM core (mainloop as a macro-like inline) =================
struct GemmPtrs {
    const uint32_t *Ah, *Al, *Bh, *Bl;
    int lda, ldb, KP;
};

__device__ __forceinline__ void gemm_mainloop(
    const GemmPtrs& P, uint32_t* smbuf, int tid, int wm, int wn, int qr, int qc,
    float acc[4][4][4])
{
    const int r0 = tid >> 5, c0 = (tid & 31) * 4;
    const int r1 = r0 + 8;
    const uint32_t smbase = (uint32_t)__cvta_generic_to_shared(smbuf);
    const int KT = (P.KP + 15) / 16;

    auto issue = [&](int kt, int buf) {
        const int rl = P.KP - kt * 16;
        const size_t ko = (size_t)kt * 16;
        const uint32_t bb = smbase + (uint32_t)buf * (8704u * 4u);
        uint32_t d0 = bb + (uint32_t)(r0 * 136 + c0) * 4u;
        uint32_t d1 = bb + (uint32_t)(r1 * 136 + c0) * 4u;
        cpa16(d0,             P.Ah + (ko + r0) * P.lda + c0, r0 < rl);
        cpa16(d1,             P.Ah + (ko + r1) * P.lda + c0, r1 < rl);
        cpa16(d0 + 2176u * 4, P.Al + (ko + r0) * P.lda + c0, r0 < rl);
        cpa16(d1 + 2176u * 4, P.Al + (ko + r1) * P.lda + c0, r1 < rl);
        cpa16(d0 + 4352u * 4, P.Bh + (ko + r0) * P.ldb + c0, r0 < rl);
        cpa16(d1 + 4352u * 4, P.Bh + (ko + r1) * P.ldb + c0, r1 < rl);
        cpa16(d0 + 6528u * 4, P.Bl + (ko + r0) * P.ldb + c0, r0 < rl);
        cpa16(d1 + 6528u * 4, P.Bl + (ko + r1) * P.ldb + c0, r1 < rl);
        cpa_commit();
    };

    issue(0, 0);
    for (int kt = 0; kt < KT; kt++) {
        const int cur = kt & 1;
        if (kt + 1 < KT) { issue(kt + 1, cur ^ 1); cpa_wait<1>(); }
        else             { cpa_wait<0>(); }
        __syncthreads();
        const uint32_t* Ah = smbuf + cur * 8704;
        const uint32_t* Al = Ah + 2176;
        const uint32_t* Bh = Ah + 4352;
        const uint32_t* Bl = Ah + 6528;
        #pragma unroll
        for (int kk = 0; kk < 2; kk++) {
            const int kb = kk * 8;
            uint32_t ah[4][4], al[4][4], bh[4][2], bl[4][2];
            #pragma unroll
            for (int mt = 0; mt < 4; mt++) {
                int R = wm * 64 + mt * 16;
                ah[mt][0] = Ah[(kb + qc) * 136 + R + qr];
                ah[mt][1] = Ah[(kb + qc) * 136 + R + qr + 8];
                ah[mt][2] = Ah[(kb + qc + 4) * 136 + R + qr];
                ah[mt][3] = Ah[(kb + qc + 4) * 136 + R + qr + 8];
                al[mt][0] = Al[(kb + qc) * 136 + R + qr];
                al[mt][1] = Al[(kb + qc) * 136 + R + qr + 8];
                al[mt][2] = Al[(kb + qc + 4) * 136 + R + qr];
                al[mt][3] = Al[(kb + qc + 4) * 136 + R + qr + 8];
            }
            #pragma unroll
            for (int nt = 0; nt < 4; nt++) {
                int C0 = wn * 32 + nt * 8;
                bh[nt][0] = Bh[(kb + qc) * 136 + C0 + qr];
                bh[nt][1] = Bh[(kb + qc + 4) * 136 + C0 + qr];
                bl[nt][0] = Bl[(kb + qc) * 136 + C0 + qr];
                bl[nt][1] = Bl[(kb + qc + 4) * 136 + C0 + qr];
            }
            #pragma unroll
            for (int mt = 0; mt < 4; mt++)
                #pragma unroll
                for (int nt = 0; nt < 4; nt++) {
                    mma16(acc[mt][nt], ah[mt], bh[nt]);
                    mma16(acc[mt][nt], al[mt], bh[nt]);
                    mma16(acc[mt][nt], ah[mt], bl[nt]);
                }
        }
        __syncthreads();
    }
}

// ================= plain / pooled GEMM =================
// POOL: embed epilogue. ACC: add Ein tile (stride sCz) before epilogue.
template<bool POOL, bool ACC>
__global__ void __launch_bounds__(256) gemm16(
    const uint32_t* __restrict__ Ahg, const uint32_t* __restrict__ Alg,
    const uint32_t* __restrict__ Bhg, const uint32_t* __restrict__ Blg,
    float* __restrict__ Cc, const float* __restrict__ bne, const float* __restrict__ Ein,
    int KP, int lda, int ldb, int ldc, size_t sAz, size_t sBz, size_t sCz)
{
    extern __shared__ __align__(16) uint32_t smbuf[];
    const int z = blockIdx.z;
    const int m0 = blockIdx.y * 128, n0 = blockIdx.x * 128;
    const int tid = threadIdx.x, lane = tid & 31, wrp = tid >> 5;
    const int wm = wrp >> 2, wn = wrp & 3;
    const int qr = lane >> 2, qc = lane & 3;

    float acc[4][4][4];
    #pragma unroll
    for (int i = 0; i < 4; i++)
        #pragma unroll
        for (int j = 0; j < 4; j++)
            #pragma unroll
            for (int q = 0; q < 4; q++) acc[i][j][q] = 0.f;

    GemmPtrs P{Ahg + z * sAz + m0, Alg + z * sAz + m0,
               Bhg + z * sBz + n0, Blg + z * sBz + n0, lda, ldb, KP};
    gemm_mainloop(P, smbuf, tid, wm, wn, qr, qc, acc);

    if (ACC) {
        const float* Eb = Ein + z * sCz;
        #pragma unroll
        for (int mt = 0; mt < 4; mt++)
            #pragma unroll
            for (int nt = 0; nt < 4; nt++) {
                int r = m0 + wm * 64 + mt * 16 + qr;
                int cc = n0 + wn * 32 + nt * 8 + 2 * qc;
                float2 e0 = *(const float2*)(Eb + (size_t)r * NPTS + cc);
                float2 e1 = *(const float2*)(Eb + (size_t)(r + 8) * NPTS + cc);
                acc[mt][nt][0] += e0.x; acc[mt][nt][1] += e0.y;
                acc[mt][nt][2] += e1.x; acc[mt][nt][3] += e1.y;
            }
    }

    if (!POOL) {
        float* Cb = Cc + z * sCz;
        #pragma unroll
        for (int mt = 0; mt < 4; mt++)
            #pragma unroll
            for (int nt = 0; nt < 4; nt++) {
                int r = m0 + wm * 64 + mt * 16 + qr;
                int cc = n0 + wn * 32 + nt * 8 + 2 * qc;
                *(float2*)(Cb + (size_t)r * ldc + cc)       = make_float2(acc[mt][nt][0], acc[mt][nt][1]);
                *(float2*)(Cb + (size_t)(r + 8) * ldc + cc) = make_float2(acc[mt][nt][2], acc[mt][nt][3]);
            }
    } else {
        __shared__ float smax[128][5], ssum[128][5];
        #pragma unroll
        for (int mt = 0; mt < 4; mt++) {
            int rl2 = wm * 64 + mt * 16 + qr;
            int o0 = m0 + rl2, o1 = o0 + 8;
            float s0 = bne[o0] / sqrtf(bne[3072 + o0] + CEPS);
            float b0 = bne[1024 + o0], u0 = bne[2048 + o0];
            float s1 = bne[o1] / sqrtf(bne[3072 + o1] + CEPS);
            float b1 = bne[1024 + o1], u1 = bne[2048 + o1];
            float mx0 = -INFINITY, sm0 = 0.f, mx1 = -INFINITY, sm1 = 0.f;
            #pragma unroll
            for (int nt = 0; nt < 4; nt++) {
                #pragma unroll
                for (int p = 0; p < 2; p++) {
                    float y0 = (acc[mt][nt][p] - u0) * s0 + b0;
                    y0 = (y0 > 0.f) ? y0 : CSLOPE * y0;
                    mx0 = fmaxf(mx0, y0); sm0 += y0;
                    float y1 = (acc[mt][nt][2 + p] - u1) * s1 + b1;
                    y1 = (y1 > 0.f) ? y1 : CSLOPE * y1;
                    mx1 = fmaxf(mx1, y1); sm1 += y1;
                }
            }
            #pragma unroll
            for (int off = 1; off <= 2; off <<= 1) {
                mx0 = fmaxf(mx0, __shfl_xor_sync(0xffffffffu, mx0, off));
                sm0 += __shfl_xor_sync(0xffffffffu, sm0, off);
                mx1 = fmaxf(mx1, __shfl_xor_sync(0xffffffffu, mx1, off));
                sm1 += __shfl_xor_sync(0xffffffffu, sm1, off);
            }
            if (qc == 0) {
                smax[rl2][wn] = mx0; ssum[rl2][wn] = sm0;
                smax[rl2 + 8][wn] = mx1; ssum[rl2 + 8][wn] = sm1;
            }
        }
        __syncthreads();
        if (tid < 128) {
            float mx = -INFINITY, sm = 0.f;
            #pragma unroll
            for (int w = 0; w < 4; w++) { mx = fmaxf(mx, smax[tid][w]); sm += ssum[tid][w]; }
            size_t o = (size_t)z * NPTS + m0 + tid;
            g_pmax[o * 8 + blockIdx.x] = mx;
            g_psum[o * 8 + blockIdx.x] = sm;
        }
    }
}

// ================= merged symmetric-gram + Z GEMM =================
// blocks [0,36): lower-triangle gram tiles (mirror-write the transpose);
// blocks [36, 36+8*ZT): Z = cat @ Wt tiles.
__global__ void __launch_bounds__(256) gramz_kernel(
    const uint32_t* __restrict__ catHo, const uint32_t* __restrict__ catLo,
    const uint32_t* __restrict__ WtHs, const uint32_t* __restrict__ WtLs,
    float* __restrict__ G, float* __restrict__ Z,
    int KP, int ZT, int ldz)
{
    extern __shared__ __align__(16) uint32_t smbuf[];
    const int z = blockIdx.z;
    const size_t sCat = (size_t)256 * NPTS;
    const int t = blockIdx.x;
    const int tid = threadIdx.x, lane = tid & 31, wrp = tid >> 5;
    const int wm = wrp >> 2, wn = wrp & 3;
    const int qr = lane >> 2, qc = lane & 3;

    const bool isg = (t < 36);
    int ia = 0, ib = 0, m0, n0, ldb_, ldc_;
    const uint32_t *Bh, *Bl;
    float* Cb;
    if (isg) {
        ib = 0;
        while ((ib + 1) * (ib + 2) / 2 <= t) ib++;
        ia = t - ib * (ib + 1) / 2;
        m0 = ia * 128; n0 = ib * 128;
        Bh = catHo + z * sCat + n0; Bl = catLo + z * sCat + n0;
        ldb_ = NPTS; ldc_ = NPTS;
        Cb = G + (size_t)z * NPTS * NPTS;
    } else {
        int t2 = t - 36;
        m0 = (t2 / ZT) * 128; n0 = (t2 % ZT) * 128;
        Bh = WtHs + n0; Bl = WtLs + n0;
        ldb_ = ldz; ldc_ = ldz;
        Cb = Z + (size_t)z * NPTS * ldz;
    }

    float acc[4][4][4];
    #pragma unroll
    for (int i = 0; i < 4; i++)
        #pragma unroll
        for (int j = 0; j < 4; j++)
            #pragma unroll
            for (int q = 0; q < 4; q++) acc[i][j][q] = 0.f;

    GemmPtrs P{catHo + z * sCat + m0, catLo + z * sCat + m0, Bh, Bl, NPTS, ldb_, KP};
    gemm_mainloop(P, smbuf, tid, wm, wn, qr, qc, acc);

    // normal write
    #pragma unroll
    for (int mt = 0; mt < 4; mt++)
        #pragma unroll
        for (int nt = 0; nt < 4; nt++) {
            int r = m0 + wm * 64 + mt * 16 + qr;
            int cc = n0 + wn * 32 + nt * 8 + 2 * qc;
            *(float2*)(Cb + (size_t)r * ldc_ + cc)       = make_float2(acc[mt][nt][0], acc[mt][nt][1]);
            *(float2*)(Cb + (size_t)(r + 8) * ldc_ + cc) = make_float2(acc[mt][nt][2], acc[mt][nt][3]);
        }

    // mirror write for off-diagonal gram tiles: stage transposed in smem
    if (isg && ia != ib) {
        float* S = (float*)smbuf;   // [c][r] with stride 132
        #pragma unroll
        for (int mt = 0; mt < 4; mt++)
            #pragma unroll
            for (int nt = 0; nt < 4; nt++) {
                int rl = wm * 64 + mt * 16 + qr;
                int cl = wn * 32 + nt * 8 + 2 * qc;
                S[(size_t)cl * 132 + rl]           = acc[mt][nt][0];
                S[(size_t)(cl + 1) * 132 + rl]     = acc[mt][nt][1];
                S[(size_t)cl * 132 + rl + 8]       = acc[mt][nt][2];
                S[(size_t)(cl + 1) * 132 + rl + 8] = acc[mt][nt][3];
            }
        __syncthreads();
        #pragma unroll
        for (int idx = tid; idx < 4096; idx += 256) {
            int row = idx >> 5, q = idx & 31;   // row = local col of original tile
            float4 v = *(const float4*)&S[(size_t)row * 132 + 4 * q];
            *(float4*)(Cb + (size_t)(n0 + row) * NPTS + m0 + 4 * q) = v;
        }
    }
}

// ================= block-1 topk: selection only =================
__global__ void __launch_bounds__(256) topk3_kernel(const float* __restrict__ x) {
    const int tid = threadIdx.x, lane = tid & 31;
    const int gw = blockIdx.x * 8 + (tid >> 5);
    const int b = gw >> 10, n = gw & 1023;
    const float* xb = x + (size_t)b * 3 * NPTS;
    float c0 = xb[n], c1 = xb[NPTS + n], c2 = xb[2 * NPTS + n];
    float d[32];
    #pragma unroll
    for (int j = 0; j < 32; j++) {
        int m = j * 32 + lane;
        float v0 = xb[m], v1 = xb[NPTS + m], v2 = xb[2 * NPTS + m];
        float dot = fmaf(v2, c2, fmaf(v1, c1, fmaf(v0, c0, 0.f)));
        float xxm = fmaf(v2, v2, fmaf(v1, v1, fmaf(v0, v0, 0.f)));
        d[j] = 2.f * dot - xxm;
    }
    int* myidx = g_idx + ((size_t)b * NPTS + n) * KNB;
    float lm = -INFINITY; int lj = 0;
    #pragma unroll
    for (int j = 0; j < 32; j++) if (d[j] > lm) { lm = d[j]; lj = j; }
    for (int k = 0; k < KNB; k++) {
        float bv = lm; int bidx = lj * 32 + lane;
        #pragma unroll
        for (int off = 16; off > 0; off >>= 1) {
            float ov = __shfl_xor_sync(0xffffffffu, bv, off);
            int   oi = __shfl_xor_sync(0xffffffffu, bidx, off);
            if (ov > bv || (ov == bv && oi < bidx)) { bv = ov; bidx = oi; }
        }
        if (lane == (bidx & 31)) {
            int jj = bidx >> 5;
            lm = -INFINITY; lj = 0;
            #pragma unroll
            for (int j = 0; j < 32; j++) {
                if (j == jj) d[j] = -INFINITY;
                if (d[j] > lm) { lm = d[j]; lj = j; }
            }
        }
        if (lane == 0) myidx[k] = bidx;
    }
}

// ================= fused topk + conv-epilogue =================
template<int O, bool WX, bool SEL>
__global__ void __launch_bounds__(256) tkcepi_kernel(const float* __restrict__ bnp, int cout_off) {
    constexpr int NCH = O / 32;
    const int tid = threadIdx.x, lane = tid & 31, wrp = tid >> 5;
    const int b = blockIdx.y;
    const int n = blockIdx.x * 8 + wrp;
    __shared__ float ys[8][O + 2];

    int mysel = 0;
    if (SEL) {
        const float* Grow = g_gram + ((size_t)b * NPTS + n) * NPTS;
        const float* xxb = g_xx + b * NPTS;
        float d[32];
        #pragma unroll
        for (int j = 0; j < 32; j++) {
            int m = j * 32 + lane;
            d[j] = 2.f * Grow[m] - xxb[m];
        }
        float lm = -INFINITY; int lj = 0;
        #pragma unroll
        for (int j = 0; j < 32; j++) if (d[j] > lm) { lm = d[j]; lj = j; }
        for (int k = 0; k < KNB; k++) {
            float bv = lm; int bidx = lj * 32 + lane;
            #pragma unroll
            for (int off = 16; off > 0; off >>= 1) {
                float ov = __shfl_xor_sync(0xffffffffu, bv, off);
                int   oi = __shfl_xor_sync(0xffffffffu, bidx, off);
                if (ov > bv || (ov == bv && oi < bidx)) { bv = ov; bidx = oi; }
            }
            if (lane == (bidx & 31)) {
                int jj = bidx >> 5;
                lm = -INFINITY; lj = 0;
                #pragma unroll
                for (int j = 0; j < 32; j++) {
                    if (j == jj) d[j] = -INFINITY;
                    if (d[j] > lm) { lm = d[j]; lj = j; }
                }
            }
            if (lane == k) mysel = bidx;
        }
    } else {
        if (lane < KNB) mysel = g_idx[((size_t)b * NPTS + n) * KNB + lane];
    }

    const int ld = 2 * O;
    const size_t rowbase = (size_t)b * NPTS;
    float mx[NCH];
    #pragma unroll
    for (int ch = 0; ch < NCH; ch++) mx[ch] = -INFINITY;
    for (int k = 0; k < KNB; k++) {
        int jk = __shfl_sync(0xffffffffu, mysel, k);
        const float* Zr = g_Z + (rowbase + jk) * ld;
        #pragma unroll
        for (int ch = 0; ch < NCH; ch++)
            mx[ch] = fmaxf(mx[ch], Zr[ch * 32 + lane]);
    }
    const float* Zc = g_Z + (rowbase + n) * ld + O;
    float xs = 0.f;
    #pragma unroll
    for (int ch = 0; ch < NCH; ch++) {
        int o = ch * 32 + lane;
        float v = mx[ch] + Zc[o];
        float scale = bnp[o] / sqrtf(bnp[3 * O + o] + CEPS);
        float y = (v - bnp[2 * O + o]) * scale + bnp[O + o];
        y = (y > 0.f) ? y : CSLOPE * y;
        ys[wrp][o] = y;
        if (WX) xs = fmaf(y, y, xs);
    }
    if (WX) {
        #pragma unroll
        for (int off = 16; off > 0; off >>= 1) xs += __shfl_xor_sync(0xffffffffu, xs, off);
        if (lane == 0) g_xx[b * NPTS + n] = xs;
    }
    __syncthreads();

    const int cp0 = cout_off >> 1;
    #pragma unroll
    for (int i = tid; i < 4 * O; i += 256) {
        int nl = i & 7, cp = i >> 3;
        float y0 = ys[nl][2 * cp], y1 = ys[nl][2 * cp + 1];
        size_t w = ((size_t)b * 256 + cp0 + cp) * NPTS + blockIdx.x * 8 + nl;
        g_catH[w] = packh(y0, y1);
        g_catL[w] = packl(y0, y1);
    }
}

// ================= pack =================
__global__ void __launch_bounds__(256) pack_kernel(
    const float* __restrict__ x,
    const float* __restrict__ w0, const float* __restrict__ w1,
    const float* __restrict__ w2, const float* __restrict__ w3,
    const float* __restrict__ we)
{
    const int tid = threadIdx.x;
    {
        __shared__ float s[32][65];
        const int bo = blockIdx.x & 31, bp = blockIdx.x >> 5;
        const int o0 = bo * 32, c0 = bp * 64;
        #pragma unroll
        for (int i = tid; i < 32 * 64; i += 256) {
            int o = i >> 6, c = i & 63;
            s[o][c] = we[(size_t)(o0 + o) * 512 + c0 + c];
        }
        __syncthreads();
        #pragma unroll
        for (int i = tid; i < 32 * 32; i += 256) {
            int p = i >> 5, o = i & 31;
            float v0 = s[o][2 * p], v1 = s[o][2 * p + 1];
            int w = ((c0 >> 1) + p) * 1024 + o0 + o;
            g_weTH[w] = packh(v0, v1);
            g_weTL[w] = packl(v0, v1);
        }
    }
    const int gstride = gridDim.x * 256;
    int gid = blockIdx.x * 256 + tid;
    for (int i = gid; i < BATCH * NPTS; i += gstride) {
        int bb = i >> 10, nn = i & 1023;
        const float* xr = x + (size_t)bb * 3 * NPTS;
        float v0 = xr[nn], v1 = xr[NPTS + nn], v2 = xr[2 * NPTS + nn];
        g_xH[(bb * 2 + 0) * NPTS + nn] = packh(v0, v1);
        g_xL[(bb * 2 + 0) * NPTS + nn] = packl(v0, v1);
        g_xH[(bb * 2 + 1) * NPTS + nn] = packh(v2, 0.f);
        g_xL[(bb * 2 + 1) * NPTS + nn] = packl(v2, 0.f);
    }
    for (int i = gid; i < WTOTU; i += gstride) {
        const float* w; int C, O, loc;
        if (i < WSEG1)      { w = w0; C = 3;   O = 64;  loc = i - WSEG0; }
        else if (i < WSEG2) { w = w1; C = 64;  O = 64;  loc = i - WSEG1; }
        else if (i < WSEG3) { w = w2; C = 64;  O = 128; loc = i - WSEG2; }
        else                { w = w3; C = 128; O = 256; loc = i - WSEG3; }
        int N2 = 2 * O, p = loc / N2, j = loc - p * N2;
        int k0 = 2 * p, k1 = 2 * p + 1;
        float v0, v1;
        if (j < O) {
            v0 = w[(size_t)j * 2 * C + k0];
            v1 = (k1 < C) ? w[(size_t)j * 2 * C + k1] : 0.f;
        } else {
            int o = j - O;
            v0 = w[(size_t)o * 2 * C + C + k0] - w[(size_t)o * 2 * C + k0];
            v1 = (k1 < C) ? (w[(size_t)o * 2 * C + C + k1] - w[(size_t)o * 2 * C + k1]) : 0.f;
        }
        g_WtH[i] = packh(v0, v1);
        g_WtL[i] = packl(v0, v1);
    }
}

// ================= fused MLP head =================
__global__ void __launch_bounds__(1024) head_kernel(
    const float* __restrict__ wf0, const float* __restrict__ bnf0,
    const float* __restrict__ wf1, const float* __restrict__ bnf1,
    const float* __restrict__ wfin, const float* __restrict__ bfin,
    float* __restrict__ out)
{
    const int b = blockIdx.x, tid = threadIdx.x;
    const int w = tid >> 5, lane = tid & 31;
    __shared__ float h0s[2048];
    __shared__ float h1s[512];
    __shared__ float h2s[256];
    {
        int o = tid;
        size_t base = ((size_t)b * NPTS + o) * 8;
        float mx = -INFINITY, sm = 0.f;
        #pragma unroll
        for (int t = 0; t < 8; t++) { mx = fmaxf(mx, g_pmax[base + t]); sm += g_psum[base + t]; }
        h0s[o] = mx;
        h0s[1024 + o] = sm * (1.0f / 1024.0f);
    }
    __syncthreads();
    for (int j = 0; j < 16; j++) {
        int o = w * 16 + j;
        const float* wr = wf0 + (size_t)o * 2048;
        float a = 0.f;
        #pragma unroll 4
        for (int c = lane * 4; c < 2048; c += 128) {
            float4 wv = *(const float4*)(wr + c);
            a = fmaf(wv.x, h0s[c], a);
            a = fmaf(wv.y, h0s[c + 1], a);
            a = fmaf(wv.z, h0s[c + 2], a);
            a = fmaf(wv.w, h0s[c + 3], a);
        }
        #pragma unroll
        for (int off = 16; off > 0; off >>= 1) a += __shfl_xor_sync(0xffffffffu, a, off);
        if (lane == 0) {
            float scale = bnf0[o] / sqrtf(bnf0[1536 + o] + CEPS);
            float y = (a - bnf0[1024 + o]) * scale + bnf0[512 + o];
            h1s[o] = (y > 0.f) ? y : CSLOPE * y;
        }
    }
    __syncthreads();
    for (int j = 0; j < 8; j++) {
        int o = w * 8 + j;
        const float* wr = wf1 + (size_t)o * 512;
        float a = 0.f;
        #pragma unroll
        for (int c = lane * 4; c < 512; c += 128) {
            float4 wv = *(const float4*)(wr + c);
            a = fmaf(wv.x, h1s[c], a);
            a = fmaf(wv.y, h1s[c + 1], a);
            a = fmaf(wv.z, h1s[c + 2], a);
            a = fmaf(wv.w, h1s[c + 3], a);
        }
        #pragma unroll
        for (int off = 16; off > 0; off >>= 1) a += __shfl_xor_sync(0xffffffffu, a, off);
        if (lane == 0) {
            float scale = bnf1[o] / sqrtf(bnf1[768 + o] + CEPS);
            float y = (a - bnf1[512 + o]) * scale + bnf1[256 + o];
            h2s[o] = (y > 0.f) ? y : CSLOPE * y;
        }
    }
    __syncthreads();
    for (int j = 0; j < 2; j++) {
        int o = w * 2 + j;
        const float* wr = wfin + (size_t)o * 256;
        float a = 0.f;
        #pragma unroll
        for (int c = lane * 4; c < 256; c += 128) {
            float4 wv = *(const float4*)(wr + c);
            a = fmaf(wv.x, h2s[c], a);
            a = fmaf(wv.y, h2s[c + 1], a);
            a = fmaf(wv.z, h2s[c + 2], a);
            a = fmaf(wv.w, h2s[c + 3], a);
        }
        #pragma unroll
        for (int off = 16; off > 0; off >>= 1) a += __shfl_xor_sync(0xffffffffu, a, off);
        if (lane == 0) out[b * 64 + o] = bfin[o] + a;
    }
}

// ================= launch =================
#define GSMEM 69632

extern "C" void kernel_launch(void* const* d_in, const int* in_sizes, int n_in,
                              void* d_out, int out_size) {
    const float* x    = (const float*)d_in[0];
    const float* w0   = (const float*)d_in[1];
    const float* w1   = (const float*)d_in[2];
    const float* w2   = (const float*)d_in[3];
    const float* w3   = (const float*)d_in[4];
    const float* bn0  = (const float*)d_in[5];
    const float* bn1  = (const float*)d_in[6];
    const float* bn2  = (const float*)d_in[7];
    const float* bn3  = (const float*)d_in[8];
    const float* we   = (const float*)d_in[9];
    const float* bne  = (const float*)d_in[10];
    const float* wf0  = (const float*)d_in[11];
    const float* bnf0 = (const float*)d_in[12];
    const float* wf1  = (const float*)d_in[13];
    const float* bnf1 = (const float*)d_in[14];
    const float* wfin = (const float*)d_in[15];
    const float* bfin = (const float*)d_in[16];

    static bool s_init = false;
    static cudaStream_t s1, s2;
    static cudaEvent_t evS, evJ0, evF2, evE;
    if (!s_init) {
        cudaStreamCreateWithFlags(&s1, cudaStreamNonBlocking);
        cudaStreamCreateWithFlags(&s2, cudaStreamNonBlocking);
        cudaEventCreateWithFlags(&evS, cudaEventDisableTiming);
        cudaEventCreateWithFlags(&evJ0, cudaEventDisableTiming);
        cudaEventCreateWithFlags(&evF2, cudaEventDisableTiming);
        cudaEventCreateWithFlags(&evE, cudaEventDisableTiming);
        cudaFuncSetAttribute(gemm16<false, false>, cudaFuncAttributeMaxDynamicSharedMemorySize, GSMEM);
        cudaFuncSetAttribute(gemm16<true, true>,   cudaFuncAttributeMaxDynamicSharedMemorySize, GSMEM);
        cudaFuncSetAttribute(gramz_kernel,         cudaFuncAttributeMaxDynamicSharedMemorySize, GSMEM);
        s_init = true;
    }

    float *Zp, *gramp, *Ep;
    uint32_t *catHp, *catLp, *WtHp, *WtLp, *weTHp, *weTLp, *xHp, *xLp;
    cudaGetSymbolAddress((void**)&Zp, g_Z);
    cudaGetSymbolAddress((void**)&gramp, g_gram);
    cudaGetSymbolAddress((void**)&Ep, g_E);
    cudaGetSymbolAddress((void**)&catHp, g_catH);
    cudaGetSymbolAddress((void**)&catLp, g_catL);
    cudaGetSymbolAddress((void**)&WtHp, g_WtH);
    cudaGetSymbolAddress((void**)&WtLp, g_WtL);
    cudaGetSymbolAddress((void**)&weTHp, g_weTH);
    cudaGetSymbolAddress((void**)&weTLp, g_weTL);
    cudaGetSymbolAddress((void**)&xHp, g_xH);
    cudaGetSymbolAddress((void**)&xLp, g_xL);

    dim3 gtk(128, BATCH);
    const size_t sCat = (size_t)256 * NPTS;
    const size_t sE = (size_t)1024 * NPTS;
    cudaStream_t s0 = 0;

    // fork: pack + Z1 on s1; topk3 on main
    cudaEventRecord(evS, s0);
    cudaStreamWaitEvent(s1, evS, 0);
    pack_kernel<<<256, 256, 0, s1>>>(x, w0, w1, w2, w3, we);
    topk3_kernel<<<1024, 256>>>(x);
    gemm16<false, false><<<dim3(1, 8, BATCH), 256, GSMEM, s1>>>(
        xHp, xLp, WtHp + WSEG0, WtLp + WSEG0, Zp, nullptr, nullptr,
        2, NPTS, 128, 128, (size_t)2 * NPTS, 0, (size_t)NPTS * 128);
    cudaEventRecord(evJ0, s1);
    cudaStreamWaitEvent(s0, evJ0, 0);
    tkcepi_kernel<64, true, false><<<gtk, 256>>>(bn0, 0);

    // block 2: merged sym-gram + Z2
    gramz_kernel<<<dim3(36 + 8 * 1, 1, BATCH), 256, GSMEM>>>(
        catHp, catLp, WtHp + WSEG1, WtLp + WSEG1, gramp, Zp, 32, 1, 128);
    tkcepi_kernel<64, true, true><<<gtk, 256>>>(bn1, 64);

    // block 3: merged sym-gram + Z3
    gramz_kernel<<<dim3(36 + 8 * 2, 1, BATCH), 256, GSMEM>>>(
        catHp + 32 * NPTS, catLp + 32 * NPTS, WtHp + WSEG2, WtLp + WSEG2, gramp, Zp, 32, 2, 256);
    tkcepi_kernel<128, true, true><<<gtk, 256>>>(bn2, 128);

    // fork E1 (first K half of embed) on s2, overlapped with block 4
    cudaEventRecord(evF2, s0);
    cudaStreamWaitEvent(s2, evF2, 0);
    gemm16<false, false><<<dim3(8, 8, BATCH), 256, GSMEM, s2>>>(
        weTHp, weTLp, catHp, catLp, Ep, nullptr, nullptr,
        128, 1024, NPTS, NPTS, 0, sCat, sE);
    cudaEventRecord(evE, s2);

    // block 4: merged sym-gram + Z4
    gramz_kernel<<<dim3(36 + 8 * 4, 1, BATCH), 256, GSMEM>>>(
        catHp + 64 * NPTS, catLp + 64 * NPTS, WtHp + WSEG3, WtLp + WSEG3, gramp, Zp, 64, 4, 512);
    tkcepi_kernel<256, false, true><<<gtk, 256>>>(bn3, 256);

    // E2: second K half + E1 accumulate + fused pool epilogue
    cudaStreamWaitEvent(s0, evE, 0);
    gemm16<true, true><<<dim3(8, 8, BATCH), 256, GSMEM>>>(
        weTHp + 128 * 1024, weTLp + 128 * 1024, catHp + 128 * NPTS, catLp + 128 * NPTS,
        nullptr, bne, Ep,
        128, 1024, NPTS, 0, 0, sCat, sE);

    // fused MLP head
    head_kernel<<<BATCH, 1024>>>(wf0, bnf0, wf1, bnf1, wfin, bfin, (float*)d_out);
}